// round 1
// baseline (speedup 1.0000x reference)
#include <cuda_runtime.h>
#include <cuda_bf16.h>
#include <math.h>

// ---------------------------------------------------------------------------
// Problem constants
// ---------------------------------------------------------------------------
#define NT   2048          // tokens (B*T)
#define DM   2048          // model dim
#define NE   64            // experts
#define TOPK 4
#define FF   512           // expert hidden
#define NS   2             // shared experts
#define SFF  2048          // shared hidden
#define CAP  256
#define NP   (NT * TOPK)   // 8192 pairs

// ---------------------------------------------------------------------------
// Scratch (device globals; no allocation allowed)
// ---------------------------------------------------------------------------
__device__ float g_logits[NT * NE];
__device__ int   g_topk_idx[NP];
__device__ float g_topk_w[NP];
__device__ int   g_tok_table[NE * CAP];
__device__ float g_w_table[NE * CAP];
__device__ int   g_counts[NE];
__device__ float g_h[NE * CAP * FF];      // expert SwiGLU hidden  (33.5 MB)
__device__ float g_hs[NS * NT * SFF];     // shared SwiGLU hidden  (33.5 MB)

// ---------------------------------------------------------------------------
// Tiled SIMT fp32 GEMM config: 64x64 block tile, BK=16, 256 threads, 4x4/thread
// All GEMMs here are C = A * B^T with both A,B K-contiguous (row-major, K inner)
// ---------------------------------------------------------------------------
#define BM 64
#define BN 64
#define BK 16

// ===========================================================================
// 1) Router logits:  logits[n,e] = x[n,:] . router_w[e,:]
// grid: (NT/BM) blocks, 256 threads. Single N-tile (NE == 64 == BN).
// ===========================================================================
__global__ __launch_bounds__(256)
void k_router_logits(const float* __restrict__ x,
                     const float* __restrict__ rw)
{
    __shared__ __align__(16) float As[BK][BM];
    __shared__ __align__(16) float Bs[BK][BN];

    const int tid = threadIdx.x;
    const int t0  = blockIdx.x * BM;
    const int lr  = tid >> 2;            // 0..63
    const int lk  = (tid & 3) * 4;       // 0,4,8,12
    const int ty4 = (tid >> 4) * 4;      // row group
    const int tx4 = (tid & 15) * 4;      // col group

    float acc[4][4];
#pragma unroll
    for (int i = 0; i < 4; i++)
#pragma unroll
        for (int j = 0; j < 4; j++) acc[i][j] = 0.f;

    for (int kt = 0; kt < DM; kt += BK) {
        float4 a = *(const float4*)(x + (size_t)(t0 + lr) * DM + kt + lk);
        As[lk+0][lr] = a.x; As[lk+1][lr] = a.y; As[lk+2][lr] = a.z; As[lk+3][lr] = a.w;
        float4 b = *(const float4*)(rw + (size_t)lr * DM + kt + lk);
        Bs[lk+0][lr] = b.x; Bs[lk+1][lr] = b.y; Bs[lk+2][lr] = b.z; Bs[lk+3][lr] = b.w;
        __syncthreads();
#pragma unroll
        for (int k = 0; k < BK; k++) {
            float4 av = *(const float4*)&As[k][ty4];
            float4 bv = *(const float4*)&Bs[k][tx4];
            float a4[4] = {av.x, av.y, av.z, av.w};
            float b4[4] = {bv.x, bv.y, bv.z, bv.w};
#pragma unroll
            for (int i = 0; i < 4; i++)
#pragma unroll
                for (int j = 0; j < 4; j++) acc[i][j] += a4[i] * b4[j];
        }
        __syncthreads();
    }
#pragma unroll
    for (int i = 0; i < 4; i++)
#pragma unroll
        for (int j = 0; j < 4; j++)
            g_logits[(size_t)(t0 + ty4 + i) * NE + tx4 + j] = acc[i][j];
}

// ===========================================================================
// 2) Top-k per token (one warp / token). Selection on logits+bias (ties ->
//    lower index); weights = softmax over selected raw logits.
// ===========================================================================
__global__ void k_topk(const float* __restrict__ bias)
{
    const int n    = blockIdx.x;
    const int lane = threadIdx.x;

    float l0 = g_logits[n * NE + lane];
    float l1 = g_logits[n * NE + 32 + lane];
    float s0 = l0 + bias[lane];
    float s1 = l1 + bias[32 + lane];

    int   ch_idx[TOPK];
    float ch_l[TOPK];

#pragma unroll
    for (int r = 0; r < TOPK; r++) {
        float v   = s0;
        int   idx = lane;
        if (s1 > v) { v = s1; idx = lane + 32; }
        // warp argmax, ties -> lower index
#pragma unroll
        for (int off = 16; off > 0; off >>= 1) {
            float ov  = __shfl_xor_sync(0xffffffffu, v, off);
            int   oi  = __shfl_xor_sync(0xffffffffu, idx, off);
            if (ov > v || (ov == v && oi < idx)) { v = ov; idx = oi; }
        }
        int owner = (idx < 32) ? idx : (idx - 32);
        float rawA = __shfl_sync(0xffffffffu, l0, owner);
        float rawB = __shfl_sync(0xffffffffu, l1, owner);
        ch_idx[r] = idx;
        ch_l[r]   = (idx < 32) ? rawA : rawB;
        if (lane == owner) {
            if (idx < 32) s0 = -INFINITY; else s1 = -INFINITY;
        }
    }

    if (lane == 0) {
        float m = ch_l[0];
#pragma unroll
        for (int r = 1; r < TOPK; r++) m = fmaxf(m, ch_l[r]);
        float w[TOPK], sum = 0.f;
#pragma unroll
        for (int r = 0; r < TOPK; r++) { w[r] = expf(ch_l[r] - m); sum += w[r]; }
        float inv = 1.f / sum;
#pragma unroll
        for (int r = 0; r < TOPK; r++) {
            g_topk_idx[n * TOPK + r] = ch_idx[r];
            g_topk_w[n * TOPK + r]   = w[r] * inv;
        }
    }
}

// ===========================================================================
// 3) Dispatch tables: stable per-expert ordered scan over pair index.
//    grid = NE blocks, 256 threads.
// ===========================================================================
__global__ __launch_bounds__(256)
void k_dispatch()
{
    const int e    = blockIdx.x;
    const int tid  = threadIdx.x;
    const int wid  = tid >> 5;
    const int lane = tid & 31;
    __shared__ int warp_tot[8];

    int base = 0;
    for (int p0 = 0; p0 < NP; p0 += 256) {
        int p    = p0 + tid;
        int ex   = g_topk_idx[p];
        bool pr  = (ex == e);
        unsigned b = __ballot_sync(0xffffffffu, pr);
        int wp = __popc(b & ((1u << lane) - 1u));
        if (lane == 0) warp_tot[wid] = __popc(b);
        __syncthreads();
        int off = base;
        for (int w = 0; w < wid; w++) off += warp_tot[w];
        int slot = off + wp;
        if (pr && slot < CAP) {
            g_tok_table[e * CAP + slot] = p >> 2;   // token id = p / TOPK
            g_w_table[e * CAP + slot]   = g_topk_w[p];
        }
        int tot = 0;
        for (int w = 0; w < 8; w++) tot += warp_tot[w];
        base += tot;
        __syncthreads();
    }
    int cnt = (base < CAP) ? base : CAP;
    if (tid == 0) g_counts[e] = cnt;
    for (int i = cnt + tid; i < CAP; i += 256) {
        g_tok_table[e * CAP + i] = 0;
        g_w_table[e * CAP + i]   = 0.f;
    }
}

// ===========================================================================
// 4) Expert gate/up + SwiGLU (dual-B fused).
//    grid: (NE, CAP/BM, FF/BN). Early-exit tiles beyond expert count.
// ===========================================================================
__global__ __launch_bounds__(256)
void k_expert_gateup(const float* __restrict__ x,
                     const float* __restrict__ gate_w,
                     const float* __restrict__ up_w)
{
    const int e  = blockIdx.x;
    const int t0 = blockIdx.y * BM;
    const int f0 = blockIdx.z * BN;
    if (t0 >= g_counts[e]) return;

    __shared__ __align__(16) float As[BK][BM];
    __shared__ __align__(16) float Bg[BK][BN];
    __shared__ __align__(16) float Bu[BK][BN];
    __shared__ int toks[BM];

    const int tid = threadIdx.x;
    const int lr  = tid >> 2;
    const int lk  = (tid & 3) * 4;
    const int ty4 = (tid >> 4) * 4;
    const int tx4 = (tid & 15) * 4;

    if (tid < BM) toks[tid] = g_tok_table[e * CAP + t0 + tid];
    __syncthreads();
    const int my_tok = toks[lr];

    float ag[4][4], au[4][4];
#pragma unroll
    for (int i = 0; i < 4; i++)
#pragma unroll
        for (int j = 0; j < 4; j++) { ag[i][j] = 0.f; au[i][j] = 0.f; }

    const float* gB = gate_w + ((size_t)e * FF + f0 + lr) * DM;
    const float* uB = up_w   + ((size_t)e * FF + f0 + lr) * DM;
    const float* aR = x + (size_t)my_tok * DM;

    for (int kt = 0; kt < DM; kt += BK) {
        float4 a = *(const float4*)(aR + kt + lk);
        As[lk+0][lr] = a.x; As[lk+1][lr] = a.y; As[lk+2][lr] = a.z; As[lk+3][lr] = a.w;
        float4 bg = *(const float4*)(gB + kt + lk);
        Bg[lk+0][lr] = bg.x; Bg[lk+1][lr] = bg.y; Bg[lk+2][lr] = bg.z; Bg[lk+3][lr] = bg.w;
        float4 bu = *(const float4*)(uB + kt + lk);
        Bu[lk+0][lr] = bu.x; Bu[lk+1][lr] = bu.y; Bu[lk+2][lr] = bu.z; Bu[lk+3][lr] = bu.w;
        __syncthreads();
#pragma unroll
        for (int k = 0; k < BK; k++) {
            float4 av  = *(const float4*)&As[k][ty4];
            float4 bgv = *(const float4*)&Bg[k][tx4];
            float4 buv = *(const float4*)&Bu[k][tx4];
            float a4[4]  = {av.x,  av.y,  av.z,  av.w};
            float g4[4]  = {bgv.x, bgv.y, bgv.z, bgv.w};
            float u4[4]  = {buv.x, buv.y, buv.z, buv.w};
#pragma unroll
            for (int i = 0; i < 4; i++)
#pragma unroll
                for (int j = 0; j < 4; j++) {
                    ag[i][j] += a4[i] * g4[j];
                    au[i][j] += a4[i] * u4[j];
                }
        }
        __syncthreads();
    }
#pragma unroll
    for (int i = 0; i < 4; i++)
#pragma unroll
        for (int j = 0; j < 4; j++) {
            float g = ag[i][j];
            float h = (g / (1.f + expf(-g))) * au[i][j];
            g_h[((size_t)e * CAP + t0 + ty4 + i) * FF + f0 + tx4 + j] = h;
        }
}

// ===========================================================================
// 5) Shared gate/up + SwiGLU.  grid: (NS, NT/BM, SFF/BN)
// ===========================================================================
__global__ __launch_bounds__(256)
void k_shared_gateup(const float* __restrict__ x,
                     const float* __restrict__ sg_w,
                     const float* __restrict__ su_w)
{
    const int s  = blockIdx.x;
    const int t0 = blockIdx.y * BM;
    const int f0 = blockIdx.z * BN;

    __shared__ __align__(16) float As[BK][BM];
    __shared__ __align__(16) float Bg[BK][BN];
    __shared__ __align__(16) float Bu[BK][BN];

    const int tid = threadIdx.x;
    const int lr  = tid >> 2;
    const int lk  = (tid & 3) * 4;
    const int ty4 = (tid >> 4) * 4;
    const int tx4 = (tid & 15) * 4;

    float ag[4][4], au[4][4];
#pragma unroll
    for (int i = 0; i < 4; i++)
#pragma unroll
        for (int j = 0; j < 4; j++) { ag[i][j] = 0.f; au[i][j] = 0.f; }

    const float* aR = x + (size_t)(t0 + lr) * DM;
    const float* gB = sg_w + ((size_t)s * SFF + f0 + lr) * DM;
    const float* uB = su_w + ((size_t)s * SFF + f0 + lr) * DM;

    for (int kt = 0; kt < DM; kt += BK) {
        float4 a = *(const float4*)(aR + kt + lk);
        As[lk+0][lr] = a.x; As[lk+1][lr] = a.y; As[lk+2][lr] = a.z; As[lk+3][lr] = a.w;
        float4 bg = *(const float4*)(gB + kt + lk);
        Bg[lk+0][lr] = bg.x; Bg[lk+1][lr] = bg.y; Bg[lk+2][lr] = bg.z; Bg[lk+3][lr] = bg.w;
        float4 bu = *(const float4*)(uB + kt + lk);
        Bu[lk+0][lr] = bu.x; Bu[lk+1][lr] = bu.y; Bu[lk+2][lr] = bu.z; Bu[lk+3][lr] = bu.w;
        __syncthreads();
#pragma unroll
        for (int k = 0; k < BK; k++) {
            float4 av  = *(const float4*)&As[k][ty4];
            float4 bgv = *(const float4*)&Bg[k][tx4];
            float4 buv = *(const float4*)&Bu[k][tx4];
            float a4[4] = {av.x,  av.y,  av.z,  av.w};
            float g4[4] = {bgv.x, bgv.y, bgv.z, bgv.w};
            float u4[4] = {buv.x, buv.y, buv.z, buv.w};
#pragma unroll
            for (int i = 0; i < 4; i++)
#pragma unroll
                for (int j = 0; j < 4; j++) {
                    ag[i][j] += a4[i] * g4[j];
                    au[i][j] += a4[i] * u4[j];
                }
        }
        __syncthreads();
    }
#pragma unroll
    for (int i = 0; i < 4; i++)
#pragma unroll
        for (int j = 0; j < 4; j++) {
            float g = ag[i][j];
            float h = (g / (1.f + expf(-g))) * au[i][j];
            g_hs[((size_t)s * NT + t0 + ty4 + i) * SFF + f0 + tx4 + j] = h;
        }
}

// ===========================================================================
// 6) Shared down: out[n,d] = sum_s hs[s,n,:] . sh_down[s,d,:]  (plain stores)
//    grid: (NT/BM, DM/BN)
// ===========================================================================
__global__ __launch_bounds__(256)
void k_shared_down(const float* __restrict__ sd_w,
                   float* __restrict__ out)
{
    const int t0 = blockIdx.x * BM;
    const int d0 = blockIdx.y * BN;

    __shared__ __align__(16) float As[BK][BM];
    __shared__ __align__(16) float Bs[BK][BN];

    const int tid = threadIdx.x;
    const int lr  = tid >> 2;
    const int lk  = (tid & 3) * 4;
    const int ty4 = (tid >> 4) * 4;
    const int tx4 = (tid & 15) * 4;

    float acc[4][4];
#pragma unroll
    for (int i = 0; i < 4; i++)
#pragma unroll
        for (int j = 0; j < 4; j++) acc[i][j] = 0.f;

    for (int s = 0; s < NS; s++) {
        const float* aR = g_hs + ((size_t)s * NT + t0 + lr) * SFF;
        const float* bR = sd_w + ((size_t)s * DM + d0 + lr) * SFF;
        for (int kt = 0; kt < SFF; kt += BK) {
            float4 a = *(const float4*)(aR + kt + lk);
            As[lk+0][lr] = a.x; As[lk+1][lr] = a.y; As[lk+2][lr] = a.z; As[lk+3][lr] = a.w;
            float4 b = *(const float4*)(bR + kt + lk);
            Bs[lk+0][lr] = b.x; Bs[lk+1][lr] = b.y; Bs[lk+2][lr] = b.z; Bs[lk+3][lr] = b.w;
            __syncthreads();
#pragma unroll
            for (int k = 0; k < BK; k++) {
                float4 av = *(const float4*)&As[k][ty4];
                float4 bv = *(const float4*)&Bs[k][tx4];
                float a4[4] = {av.x, av.y, av.z, av.w};
                float b4[4] = {bv.x, bv.y, bv.z, bv.w};
#pragma unroll
                for (int i = 0; i < 4; i++)
#pragma unroll
                    for (int j = 0; j < 4; j++) acc[i][j] += a4[i] * b4[j];
            }
            __syncthreads();
        }
    }
#pragma unroll
    for (int i = 0; i < 4; i++) {
        float4 v = make_float4(acc[i][0], acc[i][1], acc[i][2], acc[i][3]);
        *(float4*)(out + (size_t)(t0 + ty4 + i) * DM + d0 + tx4) = v;
    }
}

// ===========================================================================
// 7) Expert down + weighted scatter-add.
//    grid: (NE, CAP/BM, DM/BN). Must run AFTER k_shared_down.
// ===========================================================================
__global__ __launch_bounds__(256)
void k_expert_down(const float* __restrict__ down_w,
                   float* __restrict__ out)
{
    const int e  = blockIdx.x;
    const int t0 = blockIdx.y * BM;
    const int d0 = blockIdx.z * BN;
    if (t0 >= g_counts[e]) return;

    __shared__ __align__(16) float As[BK][BM];
    __shared__ __align__(16) float Bs[BK][BN];

    const int tid = threadIdx.x;
    const int lr  = tid >> 2;
    const int lk  = (tid & 3) * 4;
    const int ty4 = (tid >> 4) * 4;
    const int tx4 = (tid & 15) * 4;

    float acc[4][4];
#pragma unroll
    for (int i = 0; i < 4; i++)
#pragma unroll
        for (int j = 0; j < 4; j++) acc[i][j] = 0.f;

    const float* aR = g_h + ((size_t)e * CAP + t0 + lr) * FF;
    const float* bR = down_w + ((size_t)e * DM + d0 + lr) * FF;

    for (int kt = 0; kt < FF; kt += BK) {
        float4 a = *(const float4*)(aR + kt + lk);
        As[lk+0][lr] = a.x; As[lk+1][lr] = a.y; As[lk+2][lr] = a.z; As[lk+3][lr] = a.w;
        float4 b = *(const float4*)(bR + kt + lk);
        Bs[lk+0][lr] = b.x; Bs[lk+1][lr] = b.y; Bs[lk+2][lr] = b.z; Bs[lk+3][lr] = b.w;
        __syncthreads();
#pragma unroll
        for (int k = 0; k < BK; k++) {
            float4 av = *(const float4*)&As[k][ty4];
            float4 bv = *(const float4*)&Bs[k][tx4];
            float a4[4] = {av.x, av.y, av.z, av.w};
            float b4[4] = {bv.x, bv.y, bv.z, bv.w};
#pragma unroll
            for (int i = 0; i < 4; i++)
#pragma unroll
                for (int j = 0; j < 4; j++) acc[i][j] += a4[i] * b4[j];
        }
        __syncthreads();
    }
#pragma unroll
    for (int i = 0; i < 4; i++) {
        int c = t0 + ty4 + i;
        float w = g_w_table[e * CAP + c];
        if (w != 0.f) {
            int tok = g_tok_table[e * CAP + c];
            float* orow = out + (size_t)tok * DM + d0 + tx4;
#pragma unroll
            for (int j = 0; j < 4; j++)
                atomicAdd(orow + j, acc[i][j] * w);
        }
    }
}

// ===========================================================================
// Launch
// ===========================================================================
extern "C" void kernel_launch(void* const* d_in, const int* in_sizes, int n_in,
                              void* d_out, int out_size)
{
    const float* x      = (const float*)d_in[0];
    const float* rw     = (const float*)d_in[1];
    const float* rbias  = (const float*)d_in[2];
    const float* gate_w = (const float*)d_in[3];
    const float* up_w   = (const float*)d_in[4];
    const float* down_w = (const float*)d_in[5];
    const float* sg_w   = (const float*)d_in[6];
    const float* su_w   = (const float*)d_in[7];
    const float* sd_w   = (const float*)d_in[8];
    float* out = (float*)d_out;

    // 1-3: routing + dispatch
    k_router_logits<<<NT / BM, 256>>>(x, rw);
    k_topk<<<NT, 32>>>(rbias);
    k_dispatch<<<NE, 256>>>();

    // 4: expert gate/up (+SwiGLU)
    k_expert_gateup<<<dim3(NE, CAP / BM, FF / BN), 256>>>(x, gate_w, up_w);

    // 5-6: shared experts (6 initializes out with plain stores)
    k_shared_gateup<<<dim3(NS, NT / BM, SFF / BN), 256>>>(x, sg_w, su_w);
    k_shared_down<<<dim3(NT / BM, DM / BN), 256>>>(sd_w, out);

    // 7: expert down + weighted scatter (atomicAdd on top of shared output)
    k_expert_down<<<dim3(NE, CAP / BM, DM / BN), 256>>>(down_w, out);
}

// round 3
// speedup vs baseline: 1.7768x; 1.7768x over previous
#include <cuda_runtime.h>
#include <cuda_bf16.h>
#include <math.h>
#include <stdint.h>

// ---------------------------------------------------------------------------
// Problem constants
// ---------------------------------------------------------------------------
#define NT   2048
#define DM   2048
#define NE   64
#define TOPK 4
#define FF   512
#define NS   2
#define SFF  2048
#define CAP  256
#define NP   (NT * TOPK)

// ---------------------------------------------------------------------------
// Device scratch
// ---------------------------------------------------------------------------
__device__ float g_logits[NT * NE];
__device__ int   g_topk_idx[NP];
__device__ float g_topk_w[NP];
__device__ int   g_pair_slot[NP];          // e*CAP+slot or -1
__device__ int   g_tok_table[NE * CAP];
__device__ int   g_counts[NE];
__device__ float g_h [NE * CAP * FF];      // expert hidden
__device__ float g_hs[NS * NT * SFF];      // shared hidden
__device__ float g_y [(size_t)NE * CAP * DM]; // expert down output

// ---------------------------------------------------------------------------
// Helpers (non arch-gated PTX only: ldmatrix sm_75+, mma.sync bf16 sm_80+)
// ---------------------------------------------------------------------------
__device__ __forceinline__ uint32_t smem_u32(const void* p) {
    uint32_t a;
    asm("{ .reg .u64 t; cvta.to.shared.u64 t, %1; cvt.u32.u64 %0, t; }" : "=r"(a) : "l"(p));
    return a;
}
__device__ __forceinline__ void ldsm4(uint32_t r[4], uint32_t a) {
    asm volatile("ldmatrix.sync.aligned.m8n8.x4.shared.b16 {%0,%1,%2,%3}, [%4];"
        : "=r"(r[0]), "=r"(r[1]), "=r"(r[2]), "=r"(r[3]) : "r"(a));
}
__device__ __forceinline__ void mma_bf16(float c[4], const uint32_t a[4], const uint32_t b[2]) {
    asm volatile("mma.sync.aligned.m16n8k16.row.col.f32.bf16.bf16.f32 "
        "{%0,%1,%2,%3}, {%4,%5,%6,%7}, {%8,%9}, {%0,%1,%2,%3};"
        : "+f"(c[0]), "+f"(c[1]), "+f"(c[2]), "+f"(c[3])
        : "r"(a[0]), "r"(a[1]), "r"(a[2]), "r"(a[3]), "r"(b[0]), "r"(b[1]));
}
__device__ __forceinline__ uint32_t pk(float hi, float lo) {
    uint32_t d;
    asm("cvt.rn.bf16x2.f32 %0, %1, %2;" : "=r"(d) : "f"(hi), "f"(lo));
    return d;
}
// SMEM tile row stride: 72 bf16 = 144 B (16B-aligned, conflict-free ldmatrix)
#define SST_B 144
__device__ __forceinline__ void cvt_store(float4 v, char* hi, char* lo, int r, int c4) {
    uint32_t h0 = pk(v.y, v.x), h1 = pk(v.w, v.z);
    float hx = __uint_as_float(h0 << 16), hy = __uint_as_float(h0 & 0xFFFF0000u);
    float hz = __uint_as_float(h1 << 16), hw = __uint_as_float(h1 & 0xFFFF0000u);
    uint32_t l0 = pk(v.y - hy, v.x - hx), l1 = pk(v.w - hw, v.z - hz);
    uint32_t off = (uint32_t)(r * SST_B + c4 * 2);
    *(uint2*)(hi + off) = make_uint2(h0, h1);
    *(uint2*)(lo + off) = make_uint2(l0, l1);
}
__device__ __forceinline__ float silu_f(float g) { return g / (1.f + expf(-g)); }

// tile buffer sizes
#define AB 18432   // 128 rows * 144B
#define BB  9216   // 64 rows * 144B
#define GU_SMEM (2 * AB + 4 * BB)   // 73728
#define DN_SMEM (2 * AB + 2 * BB)   // 55296

// ===========================================================================
// 1) Router logits (SIMT fp32; tiny fraction of runtime)
// ===========================================================================
#define RBM 64
#define RBK 16
__global__ __launch_bounds__(256)
void k_router_logits(const float* __restrict__ x, const float* __restrict__ rw)
{
    __shared__ __align__(16) float As[RBK][RBM];
    __shared__ __align__(16) float Bs[RBK][RBM];
    const int tid = threadIdx.x;
    const int t0  = blockIdx.x * RBM;
    const int lr  = tid >> 2, lk = (tid & 3) * 4;
    const int ty4 = (tid >> 4) * 4, tx4 = (tid & 15) * 4;
    float acc[4][4];
#pragma unroll
    for (int i = 0; i < 4; i++)
#pragma unroll
        for (int j = 0; j < 4; j++) acc[i][j] = 0.f;
    for (int kt = 0; kt < DM; kt += RBK) {
        float4 a = *(const float4*)(x + (size_t)(t0 + lr) * DM + kt + lk);
        As[lk+0][lr] = a.x; As[lk+1][lr] = a.y; As[lk+2][lr] = a.z; As[lk+3][lr] = a.w;
        float4 b = *(const float4*)(rw + (size_t)lr * DM + kt + lk);
        Bs[lk+0][lr] = b.x; Bs[lk+1][lr] = b.y; Bs[lk+2][lr] = b.z; Bs[lk+3][lr] = b.w;
        __syncthreads();
#pragma unroll
        for (int k = 0; k < RBK; k++) {
            float4 av = *(const float4*)&As[k][ty4];
            float4 bv = *(const float4*)&Bs[k][tx4];
            float a4[4] = {av.x, av.y, av.z, av.w};
            float b4[4] = {bv.x, bv.y, bv.z, bv.w};
#pragma unroll
            for (int i = 0; i < 4; i++)
#pragma unroll
                for (int j = 0; j < 4; j++) acc[i][j] += a4[i] * b4[j];
        }
        __syncthreads();
    }
#pragma unroll
    for (int i = 0; i < 4; i++)
#pragma unroll
        for (int j = 0; j < 4; j++)
            g_logits[(size_t)(t0 + ty4 + i) * NE + tx4 + j] = acc[i][j];
}

// ===========================================================================
// 2) Top-k (1 warp / token)
// ===========================================================================
__global__ void k_topk(const float* __restrict__ bias)
{
    const int n = blockIdx.x, lane = threadIdx.x;
    float l0 = g_logits[n * NE + lane];
    float l1 = g_logits[n * NE + 32 + lane];
    float s0 = l0 + bias[lane];
    float s1 = l1 + bias[32 + lane];
    int ch_idx[TOPK]; float ch_l[TOPK];
#pragma unroll
    for (int r = 0; r < TOPK; r++) {
        float v = s0; int idx = lane;
        if (s1 > v) { v = s1; idx = lane + 32; }
#pragma unroll
        for (int off = 16; off > 0; off >>= 1) {
            float ov = __shfl_xor_sync(0xffffffffu, v, off);
            int   oi = __shfl_xor_sync(0xffffffffu, idx, off);
            if (ov > v || (ov == v && oi < idx)) { v = ov; idx = oi; }
        }
        int owner = (idx < 32) ? idx : (idx - 32);
        float rawA = __shfl_sync(0xffffffffu, l0, owner);
        float rawB = __shfl_sync(0xffffffffu, l1, owner);
        ch_idx[r] = idx;
        ch_l[r]   = (idx < 32) ? rawA : rawB;
        if (lane == owner) { if (idx < 32) s0 = -INFINITY; else s1 = -INFINITY; }
    }
    if (lane == 0) {
        float m = ch_l[0];
#pragma unroll
        for (int r = 1; r < TOPK; r++) m = fmaxf(m, ch_l[r]);
        float w[TOPK], sum = 0.f;
#pragma unroll
        for (int r = 0; r < TOPK; r++) { w[r] = expf(ch_l[r] - m); sum += w[r]; }
        float inv = 1.f / sum;
#pragma unroll
        for (int r = 0; r < TOPK; r++) {
            g_topk_idx[n * TOPK + r] = ch_idx[r];
            g_topk_w[n * TOPK + r]   = w[r] * inv;
        }
    }
}

// ===========================================================================
// 3) Dispatch (stable per-expert ordered scan)
// ===========================================================================
__global__ __launch_bounds__(256)
void k_dispatch()
{
    const int e = blockIdx.x, tid = threadIdx.x;
    const int wid = tid >> 5, lane = tid & 31;
    __shared__ int warp_tot[8];
    int base = 0;
    for (int p0 = 0; p0 < NP; p0 += 256) {
        int p = p0 + tid;
        bool pr = (g_topk_idx[p] == e);
        unsigned b = __ballot_sync(0xffffffffu, pr);
        int wp = __popc(b & ((1u << lane) - 1u));
        if (lane == 0) warp_tot[wid] = __popc(b);
        __syncthreads();
        int off = base;
        for (int w = 0; w < wid; w++) off += warp_tot[w];
        int slot = off + wp;
        if (pr) {
            if (slot < CAP) {
                g_tok_table[e * CAP + slot] = p >> 2;
                g_pair_slot[p] = e * CAP + slot;
            } else {
                g_pair_slot[p] = -1;
            }
        }
        int tot = 0;
        for (int w = 0; w < 8; w++) tot += warp_tot[w];
        base += tot;
        __syncthreads();
    }
    int cnt = (base < CAP) ? base : CAP;
    if (tid == 0) g_counts[e] = cnt;
    for (int i = cnt + tid; i < CAP; i += 256)
        g_tok_table[e * CAP + i] = 0;
}

// ===========================================================================
// GEMM cores: CTA 128M x 64N, K-tile 64, 512 threads (16 warps, 4Mx4N),
// warp tile 32x16, bf16 hi/lo 3-term split, fp32 accumulate.
// ===========================================================================
__device__ __forceinline__ void gu_compute(
    uint32_t uAh, uint32_t uAl, uint32_t uBgh, uint32_t uBgl,
    uint32_t uBuh, uint32_t uBul,
    uint32_t offA0, uint32_t offA1, uint32_t offB,
    float ag[2][2][4], float au[2][2][4])
{
#pragma unroll
    for (int ks = 0; ks < 4; ks++) {
        uint32_t kb = ks * 32;
        uint32_t ah[2][4], al[2][4], bgh[4], bgl[4], buh[4], bul[4];
        ldsm4(ah[0], uAh + offA0 + kb); ldsm4(ah[1], uAh + offA1 + kb);
        ldsm4(al[0], uAl + offA0 + kb); ldsm4(al[1], uAl + offA1 + kb);
        ldsm4(bgh, uBgh + offB + kb);   ldsm4(bgl, uBgl + offB + kb);
        ldsm4(buh, uBuh + offB + kb);   ldsm4(bul, uBul + offB + kb);
#pragma unroll
        for (int mf = 0; mf < 2; mf++)
#pragma unroll
            for (int nf = 0; nf < 2; nf++) {
                mma_bf16(ag[mf][nf], ah[mf], &bgh[nf * 2]);
                mma_bf16(ag[mf][nf], ah[mf], &bgl[nf * 2]);
                mma_bf16(ag[mf][nf], al[mf], &bgh[nf * 2]);
                mma_bf16(au[mf][nf], ah[mf], &buh[nf * 2]);
                mma_bf16(au[mf][nf], ah[mf], &bul[nf * 2]);
                mma_bf16(au[mf][nf], al[mf], &buh[nf * 2]);
            }
    }
}

__device__ __forceinline__ void dn_compute(
    uint32_t uAh, uint32_t uAl, uint32_t uBh, uint32_t uBl,
    uint32_t offA0, uint32_t offA1, uint32_t offB,
    float ac[2][2][4])
{
#pragma unroll
    for (int ks = 0; ks < 4; ks++) {
        uint32_t kb = ks * 32;
        uint32_t ah[2][4], al[2][4], bh[4], bl[4];
        ldsm4(ah[0], uAh + offA0 + kb); ldsm4(ah[1], uAh + offA1 + kb);
        ldsm4(al[0], uAl + offA0 + kb); ldsm4(al[1], uAl + offA1 + kb);
        ldsm4(bh, uBh + offB + kb);     ldsm4(bl, uBl + offB + kb);
#pragma unroll
        for (int mf = 0; mf < 2; mf++)
#pragma unroll
            for (int nf = 0; nf < 2; nf++) {
                mma_bf16(ac[mf][nf], ah[mf], &bh[nf * 2]);
                mma_bf16(ac[mf][nf], ah[mf], &bl[nf * 2]);
                mma_bf16(ac[mf][nf], al[mf], &bh[nf * 2]);
            }
    }
}

// ---- shared experts gate/up + SwiGLU --------------------------------------
__global__ __launch_bounds__(512)
void k_sh_gu(const float* __restrict__ x,
             const float* __restrict__ sgw, const float* __restrict__ suw)
{
    extern __shared__ char sm[];
    const int tid = threadIdx.x, wid = tid >> 5, lane = tid & 31;
    const int t0 = blockIdx.x * 128, f0 = blockIdx.y * 64, s = blockIdx.z;
    const int wm = (wid >> 2) * 32, wn = (wid & 3) * 16;

    char* Ah  = sm;            char* Al  = sm + AB;
    char* Bgh = sm + 2 * AB;   char* Bgl = Bgh + BB;
    char* Buh = Bgl + BB;      char* Bul = Buh + BB;
    uint32_t smb = smem_u32(sm);
    uint32_t uAh = smb, uAl = smb + AB, uBgh = smb + 2 * AB;
    uint32_t uBgl = uBgh + BB, uBuh = uBgl + BB, uBul = uBuh + BB;

    const uint32_t aCol = (lane >> 4) * 16;
    const uint32_t offA0 = (uint32_t)(wm + (lane & 15)) * SST_B + aCol;
    const uint32_t offA1 = offA0 + 16 * SST_B;
    const uint32_t offB  = (uint32_t)(wn + ((lane >> 4) << 3) + (lane & 7)) * SST_B
                         + ((lane >> 3) & 1) * 16;

    const float* Asrc = x   + (size_t)t0 * DM;
    const float* Gsrc = sgw + ((size_t)s * SFF + f0) * DM;
    const float* Usrc = suw + ((size_t)s * SFF + f0) * DM;

    float ag[2][2][4] = {}, au[2][2][4] = {};
    float4 pa[4], pg[2], pu[2];

#pragma unroll
    for (int ii = 0; ii < 4; ii++) {
        int i = tid + ii * 512, r = i >> 4, c4 = (i & 15) << 2;
        pa[ii] = *(const float4*)(Asrc + (size_t)r * DM + c4);
    }
#pragma unroll
    for (int ii = 0; ii < 2; ii++) {
        int i = tid + ii * 512, r = i >> 4, c4 = (i & 15) << 2;
        pg[ii] = *(const float4*)(Gsrc + (size_t)r * DM + c4);
        pu[ii] = *(const float4*)(Usrc + (size_t)r * DM + c4);
    }

    for (int it = 0; it < DM / 64; it++) {
#pragma unroll
        for (int ii = 0; ii < 4; ii++) {
            int i = tid + ii * 512, r = i >> 4, c4 = (i & 15) << 2;
            cvt_store(pa[ii], Ah, Al, r, c4);
        }
#pragma unroll
        for (int ii = 0; ii < 2; ii++) {
            int i = tid + ii * 512, r = i >> 4, c4 = (i & 15) << 2;
            cvt_store(pg[ii], Bgh, Bgl, r, c4);
            cvt_store(pu[ii], Buh, Bul, r, c4);
        }
        __syncthreads();
        if (it + 1 < DM / 64) {
            int kt = (it + 1) * 64;
#pragma unroll
            for (int ii = 0; ii < 4; ii++) {
                int i = tid + ii * 512, r = i >> 4, c4 = (i & 15) << 2;
                pa[ii] = *(const float4*)(Asrc + (size_t)r * DM + kt + c4);
            }
#pragma unroll
            for (int ii = 0; ii < 2; ii++) {
                int i = tid + ii * 512, r = i >> 4, c4 = (i & 15) << 2;
                pg[ii] = *(const float4*)(Gsrc + (size_t)r * DM + kt + c4);
                pu[ii] = *(const float4*)(Usrc + (size_t)r * DM + kt + c4);
            }
        }
        gu_compute(uAh, uAl, uBgh, uBgl, uBuh, uBul, offA0, offA1, offB, ag, au);
        __syncthreads();
    }

    const int rl = lane >> 2, cp = (lane & 3) * 2;
#pragma unroll
    for (int mf = 0; mf < 2; mf++)
#pragma unroll
        for (int nf = 0; nf < 2; nf++) {
            int row = t0 + wm + mf * 16 + rl;
            int col = f0 + wn + nf * 8 + cp;
            float* b0 = g_hs + ((size_t)s * NT + row) * SFF + col;
            float2 v0 = make_float2(silu_f(ag[mf][nf][0]) * au[mf][nf][0],
                                    silu_f(ag[mf][nf][1]) * au[mf][nf][1]);
            float2 v1 = make_float2(silu_f(ag[mf][nf][2]) * au[mf][nf][2],
                                    silu_f(ag[mf][nf][3]) * au[mf][nf][3]);
            *(float2*)b0 = v0;
            *(float2*)(b0 + (size_t)8 * SFF) = v1;
        }
}

// ---- expert gate/up (gathered rows) + SwiGLU ------------------------------
__global__ __launch_bounds__(512)
void k_ex_gu(const float* __restrict__ x,
             const float* __restrict__ gw, const float* __restrict__ uw)
{
    const int e = blockIdx.x;
    const int t0 = blockIdx.y * 128, f0 = blockIdx.z * 64;
    if (t0 >= g_counts[e]) return;

    extern __shared__ char sm[];
    __shared__ int toks[128];
    const int tid = threadIdx.x, wid = tid >> 5, lane = tid & 31;
    const int wm = (wid >> 2) * 32, wn = (wid & 3) * 16;

    char* Ah  = sm;            char* Al  = sm + AB;
    char* Bgh = sm + 2 * AB;   char* Bgl = Bgh + BB;
    char* Buh = Bgl + BB;      char* Bul = Buh + BB;
    uint32_t smb = smem_u32(sm);
    uint32_t uAh = smb, uAl = smb + AB, uBgh = smb + 2 * AB;
    uint32_t uBgl = uBgh + BB, uBuh = uBgl + BB, uBul = uBuh + BB;

    if (tid < 128) toks[tid] = g_tok_table[e * CAP + t0 + tid];
    __syncthreads();

    const uint32_t aCol = (lane >> 4) * 16;
    const uint32_t offA0 = (uint32_t)(wm + (lane & 15)) * SST_B + aCol;
    const uint32_t offA1 = offA0 + 16 * SST_B;
    const uint32_t offB  = (uint32_t)(wn + ((lane >> 4) << 3) + (lane & 7)) * SST_B
                         + ((lane >> 3) & 1) * 16;

    const float* Gsrc = gw + ((size_t)e * FF + f0) * DM;
    const float* Usrc = uw + ((size_t)e * FF + f0) * DM;

    float ag[2][2][4] = {}, au[2][2][4] = {};
    float4 pa[4], pg[2], pu[2];

#pragma unroll
    for (int ii = 0; ii < 4; ii++) {
        int i = tid + ii * 512, r = i >> 4, c4 = (i & 15) << 2;
        pa[ii] = *(const float4*)(x + (size_t)toks[r] * DM + c4);
    }
#pragma unroll
    for (int ii = 0; ii < 2; ii++) {
        int i = tid + ii * 512, r = i >> 4, c4 = (i & 15) << 2;
        pg[ii] = *(const float4*)(Gsrc + (size_t)r * DM + c4);
        pu[ii] = *(const float4*)(Usrc + (size_t)r * DM + c4);
    }

    for (int it = 0; it < DM / 64; it++) {
#pragma unroll
        for (int ii = 0; ii < 4; ii++) {
            int i = tid + ii * 512, r = i >> 4, c4 = (i & 15) << 2;
            cvt_store(pa[ii], Ah, Al, r, c4);
        }
#pragma unroll
        for (int ii = 0; ii < 2; ii++) {
            int i = tid + ii * 512, r = i >> 4, c4 = (i & 15) << 2;
            cvt_store(pg[ii], Bgh, Bgl, r, c4);
            cvt_store(pu[ii], Buh, Bul, r, c4);
        }
        __syncthreads();
        if (it + 1 < DM / 64) {
            int kt = (it + 1) * 64;
#pragma unroll
            for (int ii = 0; ii < 4; ii++) {
                int i = tid + ii * 512, r = i >> 4, c4 = (i & 15) << 2;
                pa[ii] = *(const float4*)(x + (size_t)toks[r] * DM + kt + c4);
            }
#pragma unroll
            for (int ii = 0; ii < 2; ii++) {
                int i = tid + ii * 512, r = i >> 4, c4 = (i & 15) << 2;
                pg[ii] = *(const float4*)(Gsrc + (size_t)r * DM + kt + c4);
                pu[ii] = *(const float4*)(Usrc + (size_t)r * DM + kt + c4);
            }
        }
        gu_compute(uAh, uAl, uBgh, uBgl, uBuh, uBul, offA0, offA1, offB, ag, au);
        __syncthreads();
    }

    const int rl = lane >> 2, cp = (lane & 3) * 2;
#pragma unroll
    for (int mf = 0; mf < 2; mf++)
#pragma unroll
        for (int nf = 0; nf < 2; nf++) {
            int row = t0 + wm + mf * 16 + rl;
            int col = f0 + wn + nf * 8 + cp;
            float* b0 = g_h + ((size_t)e * CAP + row) * FF + col;
            float2 v0 = make_float2(silu_f(ag[mf][nf][0]) * au[mf][nf][0],
                                    silu_f(ag[mf][nf][1]) * au[mf][nf][1]);
            float2 v1 = make_float2(silu_f(ag[mf][nf][2]) * au[mf][nf][2],
                                    silu_f(ag[mf][nf][3]) * au[mf][nf][3]);
            *(float2*)b0 = v0;
            *(float2*)(b0 + (size_t)8 * FF) = v1;
        }
}

// ---- shared down: out = sum_s hs_s @ sd_s^T  (initializes out) ------------
__global__ __launch_bounds__(512)
void k_sh_dn(const float* __restrict__ sdw, float* __restrict__ out)
{
    extern __shared__ char sm[];
    const int tid = threadIdx.x, wid = tid >> 5, lane = tid & 31;
    const int t0 = blockIdx.x * 128, d0 = blockIdx.y * 64;
    const int wm = (wid >> 2) * 32, wn = (wid & 3) * 16;

    char* Ah = sm;          char* Al = sm + AB;
    char* Bh = sm + 2 * AB; char* Bl = Bh + BB;
    uint32_t smb = smem_u32(sm);
    uint32_t uAh = smb, uAl = smb + AB, uBh = smb + 2 * AB, uBl = uBh + BB;

    const uint32_t aCol = (lane >> 4) * 16;
    const uint32_t offA0 = (uint32_t)(wm + (lane & 15)) * SST_B + aCol;
    const uint32_t offA1 = offA0 + 16 * SST_B;
    const uint32_t offB  = (uint32_t)(wn + ((lane >> 4) << 3) + (lane & 7)) * SST_B
                         + ((lane >> 3) & 1) * 16;

    float ac[2][2][4] = {};
    float4 pa[4], pb[2];

    // it in [0, 64): s = it>>5, kt = (it&31)*64
#pragma unroll
    for (int ii = 0; ii < 4; ii++) {
        int i = tid + ii * 512, r = i >> 4, c4 = (i & 15) << 2;
        pa[ii] = *(const float4*)(g_hs + ((size_t)0 * NT + t0 + r) * SFF + c4);
    }
#pragma unroll
    for (int ii = 0; ii < 2; ii++) {
        int i = tid + ii * 512, r = i >> 4, c4 = (i & 15) << 2;
        pb[ii] = *(const float4*)(sdw + ((size_t)0 * DM + d0 + r) * SFF + c4);
    }

    for (int it = 0; it < 64; it++) {
#pragma unroll
        for (int ii = 0; ii < 4; ii++) {
            int i = tid + ii * 512, r = i >> 4, c4 = (i & 15) << 2;
            cvt_store(pa[ii], Ah, Al, r, c4);
        }
#pragma unroll
        for (int ii = 0; ii < 2; ii++) {
            int i = tid + ii * 512, r = i >> 4, c4 = (i & 15) << 2;
            cvt_store(pb[ii], Bh, Bl, r, c4);
        }
        __syncthreads();
        if (it + 1 < 64) {
            int s  = (it + 1) >> 5;
            int kt = ((it + 1) & 31) * 64;
#pragma unroll
            for (int ii = 0; ii < 4; ii++) {
                int i = tid + ii * 512, r = i >> 4, c4 = (i & 15) << 2;
                pa[ii] = *(const float4*)(g_hs + ((size_t)s * NT + t0 + r) * SFF + kt + c4);
            }
#pragma unroll
            for (int ii = 0; ii < 2; ii++) {
                int i = tid + ii * 512, r = i >> 4, c4 = (i & 15) << 2;
                pb[ii] = *(const float4*)(sdw + ((size_t)s * DM + d0 + r) * SFF + kt + c4);
            }
        }
        dn_compute(uAh, uAl, uBh, uBl, offA0, offA1, offB, ac);
        __syncthreads();
    }

    const int rl = lane >> 2, cp = (lane & 3) * 2;
#pragma unroll
    for (int mf = 0; mf < 2; mf++)
#pragma unroll
        for (int nf = 0; nf < 2; nf++) {
            int row = t0 + wm + mf * 16 + rl;
            int col = d0 + wn + nf * 8 + cp;
            float* b0 = out + (size_t)row * DM + col;
            *(float2*)b0 = make_float2(ac[mf][nf][0], ac[mf][nf][1]);
            *(float2*)(b0 + (size_t)8 * DM) = make_float2(ac[mf][nf][2], ac[mf][nf][3]);
        }
}

// ---- expert down: y = h @ down^T  (plain stores to g_y) -------------------
__global__ __launch_bounds__(512)
void k_ex_dn(const float* __restrict__ dw)
{
    const int e = blockIdx.x;
    const int t0 = blockIdx.y * 128, d0 = blockIdx.z * 64;
    if (t0 >= g_counts[e]) return;

    extern __shared__ char sm[];
    const int tid = threadIdx.x, wid = tid >> 5, lane = tid & 31;
    const int wm = (wid >> 2) * 32, wn = (wid & 3) * 16;

    char* Ah = sm;          char* Al = sm + AB;
    char* Bh = sm + 2 * AB; char* Bl = Bh + BB;
    uint32_t smb = smem_u32(sm);
    uint32_t uAh = smb, uAl = smb + AB, uBh = smb + 2 * AB, uBl = uBh + BB;

    const uint32_t aCol = (lane >> 4) * 16;
    const uint32_t offA0 = (uint32_t)(wm + (lane & 15)) * SST_B + aCol;
    const uint32_t offA1 = offA0 + 16 * SST_B;
    const uint32_t offB  = (uint32_t)(wn + ((lane >> 4) << 3) + (lane & 7)) * SST_B
                         + ((lane >> 3) & 1) * 16;

    const float* Asrc = g_h + ((size_t)e * CAP + t0) * FF;
    const float* Bsrc = dw  + ((size_t)e * DM + d0) * FF;

    float ac[2][2][4] = {};
    float4 pa[4], pb[2];

#pragma unroll
    for (int ii = 0; ii < 4; ii++) {
        int i = tid + ii * 512, r = i >> 4, c4 = (i & 15) << 2;
        pa[ii] = *(const float4*)(Asrc + (size_t)r * FF + c4);
    }
#pragma unroll
    for (int ii = 0; ii < 2; ii++) {
        int i = tid + ii * 512, r = i >> 4, c4 = (i & 15) << 2;
        pb[ii] = *(const float4*)(Bsrc + (size_t)r * FF + c4);
    }

    for (int it = 0; it < FF / 64; it++) {
#pragma unroll
        for (int ii = 0; ii < 4; ii++) {
            int i = tid + ii * 512, r = i >> 4, c4 = (i & 15) << 2;
            cvt_store(pa[ii], Ah, Al, r, c4);
        }
#pragma unroll
        for (int ii = 0; ii < 2; ii++) {
            int i = tid + ii * 512, r = i >> 4, c4 = (i & 15) << 2;
            cvt_store(pb[ii], Bh, Bl, r, c4);
        }
        __syncthreads();
        if (it + 1 < FF / 64) {
            int kt = (it + 1) * 64;
#pragma unroll
            for (int ii = 0; ii < 4; ii++) {
                int i = tid + ii * 512, r = i >> 4, c4 = (i & 15) << 2;
                pa[ii] = *(const float4*)(Asrc + (size_t)r * FF + kt + c4);
            }
#pragma unroll
            for (int ii = 0; ii < 2; ii++) {
                int i = tid + ii * 512, r = i >> 4, c4 = (i & 15) << 2;
                pb[ii] = *(const float4*)(Bsrc + (size_t)r * FF + kt + c4);
            }
        }
        dn_compute(uAh, uAl, uBh, uBl, offA0, offA1, offB, ac);
        __syncthreads();
    }

    const int rl = lane >> 2, cp = (lane & 3) * 2;
#pragma unroll
    for (int mf = 0; mf < 2; mf++)
#pragma unroll
        for (int nf = 0; nf < 2; nf++) {
            int row = t0 + wm + mf * 16 + rl;
            int col = d0 + wn + nf * 8 + cp;
            float* b0 = g_y + ((size_t)e * CAP + row) * DM + col;
            *(float2*)b0 = make_float2(ac[mf][nf][0], ac[mf][nf][1]);
            *(float2*)(b0 + (size_t)8 * DM) = make_float2(ac[mf][nf][2], ac[mf][nf][3]);
        }
}

// ===========================================================================
// Combine: out[n] += sum_r w_r * y[slot_r]   (no atomics)
// ===========================================================================
__global__ __launch_bounds__(256)
void k_combine(float* __restrict__ out)
{
    const int n = blockIdx.x, tid = threadIdx.x;
    int   sl[TOPK];
    float w[TOPK];
#pragma unroll
    for (int r = 0; r < TOPK; r++) {
        sl[r] = g_pair_slot[n * TOPK + r];
        w[r]  = g_topk_w[n * TOPK + r];
    }
    float* orow = out + (size_t)n * DM;
#pragma unroll
    for (int d = tid * 4; d < DM; d += 1024) {
        float4 acc = *(float4*)(orow + d);
#pragma unroll
        for (int r = 0; r < TOPK; r++) {
            if (sl[r] >= 0) {
                float4 yv = *(const float4*)(g_y + (size_t)sl[r] * DM + d);
                acc.x += w[r] * yv.x; acc.y += w[r] * yv.y;
                acc.z += w[r] * yv.z; acc.w += w[r] * yv.w;
            }
        }
        *(float4*)(orow + d) = acc;
    }
}

// ===========================================================================
// Launch
// ===========================================================================
extern "C" void kernel_launch(void* const* d_in, const int* in_sizes, int n_in,
                              void* d_out, int out_size)
{
    const float* x      = (const float*)d_in[0];
    const float* rw     = (const float*)d_in[1];
    const float* rbias  = (const float*)d_in[2];
    const float* gate_w = (const float*)d_in[3];
    const float* up_w   = (const float*)d_in[4];
    const float* down_w = (const float*)d_in[5];
    const float* sg_w   = (const float*)d_in[6];
    const float* su_w   = (const float*)d_in[7];
    const float* sd_w   = (const float*)d_in[8];
    float* out = (float*)d_out;

    cudaFuncSetAttribute(k_sh_gu, cudaFuncAttributeMaxDynamicSharedMemorySize, GU_SMEM);
    cudaFuncSetAttribute(k_ex_gu, cudaFuncAttributeMaxDynamicSharedMemorySize, GU_SMEM);
    cudaFuncSetAttribute(k_sh_dn, cudaFuncAttributeMaxDynamicSharedMemorySize, DN_SMEM);
    cudaFuncSetAttribute(k_ex_dn, cudaFuncAttributeMaxDynamicSharedMemorySize, DN_SMEM);

    k_router_logits<<<NT / RBM, 256>>>(x, rw);
    k_topk<<<NT, 32>>>(rbias);
    k_dispatch<<<NE, 256>>>();

    k_ex_gu<<<dim3(NE, CAP / 128, FF / 64), 512, GU_SMEM>>>(x, gate_w, up_w);
    k_sh_gu<<<dim3(NT / 128, SFF / 64, NS), 512, GU_SMEM>>>(x, sg_w, su_w);

    k_sh_dn<<<dim3(NT / 128, DM / 64), 512, DN_SMEM>>>(sd_w, out);
    k_ex_dn<<<dim3(NE, CAP / 128, DM / 64), 512, DN_SMEM>>>(down_w);

    k_combine<<<NT, 256>>>(out);
}

// round 4
// speedup vs baseline: 3.4083x; 1.9182x over previous
#include <cuda_runtime.h>
#include <cuda_fp16.h>
#include <math.h>
#include <stdint.h>

// ---------------------------------------------------------------------------
// Problem constants
// ---------------------------------------------------------------------------
#define NT   2048
#define DM   2048
#define NE   64
#define TOPK 4
#define FF   512
#define NS   2
#define SFF  2048
#define CAP  256
#define NP   (NT * TOPK)

// ---------------------------------------------------------------------------
// Device scratch
// ---------------------------------------------------------------------------
__device__ float g_logits[NT * NE];
__device__ int   g_topk_idx[NP];
__device__ float g_topk_w[NP];
__device__ int   g_pair_slot[NP];
__device__ int   g_tok_table[NE * CAP];
__device__ int   g_counts[NE];
__device__ float g_h [NE * CAP * FF];
__device__ float g_hs[NS * NT * SFF];
__device__ float g_y [(size_t)NE * CAP * DM];

// ---------------------------------------------------------------------------
// Helpers
// ---------------------------------------------------------------------------
__device__ __forceinline__ uint32_t smem_u32(const void* p) {
    uint32_t a;
    asm("{ .reg .u64 t; cvta.to.shared.u64 t, %1; cvt.u32.u64 %0, t; }" : "=r"(a) : "l"(p));
    return a;
}
__device__ __forceinline__ void ldsm4(uint32_t r[4], uint32_t a) {
    asm volatile("ldmatrix.sync.aligned.m8n8.x4.shared.b16 {%0,%1,%2,%3}, [%4];"
        : "=r"(r[0]), "=r"(r[1]), "=r"(r[2]), "=r"(r[3]) : "r"(a));
}
__device__ __forceinline__ void mma_f16(float c[4], const uint32_t a[4], const uint32_t b[2]) {
    asm volatile("mma.sync.aligned.m16n8k16.row.col.f32.f16.f16.f32 "
        "{%0,%1,%2,%3}, {%4,%5,%6,%7}, {%8,%9}, {%0,%1,%2,%3};"
        : "+f"(c[0]), "+f"(c[1]), "+f"(c[2]), "+f"(c[3])
        : "r"(a[0]), "r"(a[1]), "r"(a[2]), "r"(a[3]), "r"(b[0]), "r"(b[1]));
}
__device__ __forceinline__ uint32_t h2u(__half2 h) { return *(uint32_t*)&h; }

// SMEM tile row stride: 72 halves = 144 B (16B-aligned, conflict-free ldmatrix)
#define SST_B 144

// A: fp16 single precision (unsplit)
__device__ __forceinline__ void cvt_storeA(float4 v, char* hi, int r, int c4) {
    __half2 h0 = __floats2half2_rn(v.x, v.y);
    __half2 h1 = __floats2half2_rn(v.z, v.w);
    *(uint2*)(hi + (uint32_t)(r * SST_B + c4 * 2)) = make_uint2(h2u(h0), h2u(h1));
}
// B: fp16 hi + lo residual
__device__ __forceinline__ void cvt_storeB(float4 v, char* hi, char* lo, int r, int c4) {
    __half2 h0 = __floats2half2_rn(v.x, v.y);
    __half2 h1 = __floats2half2_rn(v.z, v.w);
    float2 f0 = __half22float2(h0), f1 = __half22float2(h1);
    __half2 l0 = __floats2half2_rn(v.x - f0.x, v.y - f0.y);
    __half2 l1 = __floats2half2_rn(v.z - f1.x, v.w - f1.y);
    uint32_t off = (uint32_t)(r * SST_B + c4 * 2);
    *(uint2*)(hi + off) = make_uint2(h2u(h0), h2u(h1));
    *(uint2*)(lo + off) = make_uint2(h2u(l0), h2u(l1));
}
__device__ __forceinline__ float silu_f(float g) { return g / (1.f + expf(-g)); }

// Stage layouts (per pipeline stage)
#define ABYTES 18432          // 128 rows * 144B
#define BBYTES  9216          // 64 rows * 144B
// GU stage: A | Bgh | Bgl | Buh | Bul
#define GU_STG (ABYTES + 4 * BBYTES)     // 55296
#define GU_SMEM (2 * GU_STG)             // 110592
// DN stage: A | Bh | Bl
#define DN_STG (ABYTES + 2 * BBYTES)     // 36864
#define DN_SMEM (2 * DN_STG)             // 73728

// ===========================================================================
// 1) Router logits (SIMT fp32)
// ===========================================================================
#define RBM 64
#define RBK 16
__global__ __launch_bounds__(256)
void k_router_logits(const float* __restrict__ x, const float* __restrict__ rw)
{
    __shared__ __align__(16) float As[RBK][RBM];
    __shared__ __align__(16) float Bs[RBK][RBM];
    const int tid = threadIdx.x;
    const int t0  = blockIdx.x * RBM;
    const int lr  = tid >> 2, lk = (tid & 3) * 4;
    const int ty4 = (tid >> 4) * 4, tx4 = (tid & 15) * 4;
    float acc[4][4];
#pragma unroll
    for (int i = 0; i < 4; i++)
#pragma unroll
        for (int j = 0; j < 4; j++) acc[i][j] = 0.f;
    for (int kt = 0; kt < DM; kt += RBK) {
        float4 a = *(const float4*)(x + (size_t)(t0 + lr) * DM + kt + lk);
        As[lk+0][lr] = a.x; As[lk+1][lr] = a.y; As[lk+2][lr] = a.z; As[lk+3][lr] = a.w;
        float4 b = *(const float4*)(rw + (size_t)lr * DM + kt + lk);
        Bs[lk+0][lr] = b.x; Bs[lk+1][lr] = b.y; Bs[lk+2][lr] = b.z; Bs[lk+3][lr] = b.w;
        __syncthreads();
#pragma unroll
        for (int k = 0; k < RBK; k++) {
            float4 av = *(const float4*)&As[k][ty4];
            float4 bv = *(const float4*)&Bs[k][tx4];
            float a4[4] = {av.x, av.y, av.z, av.w};
            float b4[4] = {bv.x, bv.y, bv.z, bv.w};
#pragma unroll
            for (int i = 0; i < 4; i++)
#pragma unroll
                for (int j = 0; j < 4; j++) acc[i][j] += a4[i] * b4[j];
        }
        __syncthreads();
    }
#pragma unroll
    for (int i = 0; i < 4; i++)
#pragma unroll
        for (int j = 0; j < 4; j++)
            g_logits[(size_t)(t0 + ty4 + i) * NE + tx4 + j] = acc[i][j];
}

// ===========================================================================
// 2) Top-k (1 warp / token)
// ===========================================================================
__global__ void k_topk(const float* __restrict__ bias)
{
    const int n = blockIdx.x, lane = threadIdx.x;
    float l0 = g_logits[n * NE + lane];
    float l1 = g_logits[n * NE + 32 + lane];
    float s0 = l0 + bias[lane];
    float s1 = l1 + bias[32 + lane];
    int ch_idx[TOPK]; float ch_l[TOPK];
#pragma unroll
    for (int r = 0; r < TOPK; r++) {
        float v = s0; int idx = lane;
        if (s1 > v) { v = s1; idx = lane + 32; }
#pragma unroll
        for (int off = 16; off > 0; off >>= 1) {
            float ov = __shfl_xor_sync(0xffffffffu, v, off);
            int   oi = __shfl_xor_sync(0xffffffffu, idx, off);
            if (ov > v || (ov == v && oi < idx)) { v = ov; idx = oi; }
        }
        int owner = (idx < 32) ? idx : (idx - 32);
        float rawA = __shfl_sync(0xffffffffu, l0, owner);
        float rawB = __shfl_sync(0xffffffffu, l1, owner);
        ch_idx[r] = idx;
        ch_l[r]   = (idx < 32) ? rawA : rawB;
        if (lane == owner) { if (idx < 32) s0 = -INFINITY; else s1 = -INFINITY; }
    }
    if (lane == 0) {
        float m = ch_l[0];
#pragma unroll
        for (int r = 1; r < TOPK; r++) m = fmaxf(m, ch_l[r]);
        float w[TOPK], sum = 0.f;
#pragma unroll
        for (int r = 0; r < TOPK; r++) { w[r] = expf(ch_l[r] - m); sum += w[r]; }
        float inv = 1.f / sum;
#pragma unroll
        for (int r = 0; r < TOPK; r++) {
            g_topk_idx[n * TOPK + r] = ch_idx[r];
            g_topk_w[n * TOPK + r]   = w[r] * inv;
        }
    }
}

// ===========================================================================
// 3) Dispatch
// ===========================================================================
__global__ __launch_bounds__(256)
void k_dispatch()
{
    const int e = blockIdx.x, tid = threadIdx.x;
    const int wid = tid >> 5, lane = tid & 31;
    __shared__ int warp_tot[8];
    int base = 0;
    for (int p0 = 0; p0 < NP; p0 += 256) {
        int p = p0 + tid;
        bool pr = (g_topk_idx[p] == e);
        unsigned b = __ballot_sync(0xffffffffu, pr);
        int wp = __popc(b & ((1u << lane) - 1u));
        if (lane == 0) warp_tot[wid] = __popc(b);
        __syncthreads();
        int off = base;
        for (int w = 0; w < wid; w++) off += warp_tot[w];
        int slot = off + wp;
        if (pr) {
            if (slot < CAP) {
                g_tok_table[e * CAP + slot] = p >> 2;
                g_pair_slot[p] = e * CAP + slot;
            } else {
                g_pair_slot[p] = -1;
            }
        }
        int tot = 0;
        for (int w = 0; w < 8; w++) tot += warp_tot[w];
        base += tot;
        __syncthreads();
    }
    int cnt = (base < CAP) ? base : CAP;
    if (tid == 0) g_counts[e] = cnt;
    for (int i = cnt + tid; i < CAP; i += 256)
        g_tok_table[e * CAP + i] = 0;
}

// ===========================================================================
// GEMM compute cores (fp16: A single, B hi+lo). CTA 128Mx64N, K-tile 64,
// 512 threads (16 warps, 4Mx4N), warp tile 32x16.
// ===========================================================================
__device__ __forceinline__ void gu_compute(
    uint32_t ub, uint32_t offA0, uint32_t offA1, uint32_t offB,
    float ag[2][2][4], float au[2][2][4])
{
    const uint32_t uA = ub, uBgh = ub + ABYTES, uBgl = uBgh + BBYTES;
    const uint32_t uBuh = uBgl + BBYTES, uBul = uBuh + BBYTES;
#pragma unroll
    for (int ks = 0; ks < 4; ks++) {
        uint32_t kb = ks * 32;
        uint32_t ah[2][4], bgh[4], bgl[4], buh[4], bul[4];
        ldsm4(ah[0], uA + offA0 + kb); ldsm4(ah[1], uA + offA1 + kb);
        ldsm4(bgh, uBgh + offB + kb);  ldsm4(bgl, uBgl + offB + kb);
        ldsm4(buh, uBuh + offB + kb);  ldsm4(bul, uBul + offB + kb);
#pragma unroll
        for (int mf = 0; mf < 2; mf++)
#pragma unroll
            for (int nf = 0; nf < 2; nf++) {
                mma_f16(ag[mf][nf], ah[mf], &bgh[nf * 2]);
                mma_f16(ag[mf][nf], ah[mf], &bgl[nf * 2]);
                mma_f16(au[mf][nf], ah[mf], &buh[nf * 2]);
                mma_f16(au[mf][nf], ah[mf], &bul[nf * 2]);
            }
    }
}

__device__ __forceinline__ void dn_compute(
    uint32_t ub, uint32_t offA0, uint32_t offA1, uint32_t offB,
    float ac[2][2][4])
{
    const uint32_t uA = ub, uBh = ub + ABYTES, uBl = uBh + BBYTES;
#pragma unroll
    for (int ks = 0; ks < 4; ks++) {
        uint32_t kb = ks * 32;
        uint32_t ah[2][4], bh[4], bl[4];
        ldsm4(ah[0], uA + offA0 + kb); ldsm4(ah[1], uA + offA1 + kb);
        ldsm4(bh, uBh + offB + kb);    ldsm4(bl, uBl + offB + kb);
#pragma unroll
        for (int mf = 0; mf < 2; mf++)
#pragma unroll
            for (int nf = 0; nf < 2; nf++) {
                mma_f16(ac[mf][nf], ah[mf], &bh[nf * 2]);
                mma_f16(ac[mf][nf], ah[mf], &bl[nf * 2]);
            }
    }
}

// ---- shared experts gate/up + SwiGLU --------------------------------------
__global__ __launch_bounds__(512)
void k_sh_gu(const float* __restrict__ x,
             const float* __restrict__ sgw, const float* __restrict__ suw)
{
    extern __shared__ char sm[];
    const int tid = threadIdx.x, wid = tid >> 5, lane = tid & 31;
    const int t0 = blockIdx.x * 128, f0 = blockIdx.y * 64, s = blockIdx.z;
    const int wm = (wid >> 2) * 32, wn = (wid & 3) * 16;
    uint32_t smb = smem_u32(sm);

    const uint32_t aCol = (lane >> 4) * 16;
    const uint32_t offA0 = (uint32_t)(wm + (lane & 15)) * SST_B + aCol;
    const uint32_t offA1 = offA0 + 16 * SST_B;
    const uint32_t offB  = (uint32_t)(wn + ((lane >> 4) << 3) + (lane & 7)) * SST_B
                         + ((lane >> 3) & 1) * 16;

    const float* Asrc = x   + (size_t)t0 * DM;
    const float* Gsrc = sgw + ((size_t)s * SFF + f0) * DM;
    const float* Usrc = suw + ((size_t)s * SFF + f0) * DM;

    float ag[2][2][4] = {}, au[2][2][4] = {};
    float4 pa[4], pg[2], pu[2];

#pragma unroll
    for (int ii = 0; ii < 4; ii++) {
        int i = tid + ii * 512, r = i >> 4, c4 = (i & 15) << 2;
        pa[ii] = *(const float4*)(Asrc + (size_t)r * DM + c4);
    }
#pragma unroll
    for (int ii = 0; ii < 2; ii++) {
        int i = tid + ii * 512, r = i >> 4, c4 = (i & 15) << 2;
        pg[ii] = *(const float4*)(Gsrc + (size_t)r * DM + c4);
        pu[ii] = *(const float4*)(Usrc + (size_t)r * DM + c4);
    }
    {
        char* A  = sm;             char* Bgh = sm + ABYTES;
        char* Bgl = Bgh + BBYTES;  char* Buh = Bgl + BBYTES; char* Bul = Buh + BBYTES;
#pragma unroll
        for (int ii = 0; ii < 4; ii++) {
            int i = tid + ii * 512, r = i >> 4, c4 = (i & 15) << 2;
            cvt_storeA(pa[ii], A, r, c4);
        }
#pragma unroll
        for (int ii = 0; ii < 2; ii++) {
            int i = tid + ii * 512, r = i >> 4, c4 = (i & 15) << 2;
            cvt_storeB(pg[ii], Bgh, Bgl, r, c4);
            cvt_storeB(pu[ii], Buh, Bul, r, c4);
        }
    }
    __syncthreads();

    for (int it = 0; it < DM / 64; it++) {
        if (it + 1 < DM / 64) {
            int kt = (it + 1) * 64;
#pragma unroll
            for (int ii = 0; ii < 4; ii++) {
                int i = tid + ii * 512, r = i >> 4, c4 = (i & 15) << 2;
                pa[ii] = *(const float4*)(Asrc + (size_t)r * DM + kt + c4);
            }
#pragma unroll
            for (int ii = 0; ii < 2; ii++) {
                int i = tid + ii * 512, r = i >> 4, c4 = (i & 15) << 2;
                pg[ii] = *(const float4*)(Gsrc + (size_t)r * DM + kt + c4);
                pu[ii] = *(const float4*)(Usrc + (size_t)r * DM + kt + c4);
            }
        }
        gu_compute(smb + (it & 1) * GU_STG, offA0, offA1, offB, ag, au);
        if (it + 1 < DM / 64) {
            char* base = sm + ((it + 1) & 1) * GU_STG;
            char* A  = base;            char* Bgh = base + ABYTES;
            char* Bgl = Bgh + BBYTES;   char* Buh = Bgl + BBYTES; char* Bul = Buh + BBYTES;
#pragma unroll
            for (int ii = 0; ii < 4; ii++) {
                int i = tid + ii * 512, r = i >> 4, c4 = (i & 15) << 2;
                cvt_storeA(pa[ii], A, r, c4);
            }
#pragma unroll
            for (int ii = 0; ii < 2; ii++) {
                int i = tid + ii * 512, r = i >> 4, c4 = (i & 15) << 2;
                cvt_storeB(pg[ii], Bgh, Bgl, r, c4);
                cvt_storeB(pu[ii], Buh, Bul, r, c4);
            }
        }
        __syncthreads();
    }

    const int rl = lane >> 2, cp = (lane & 3) * 2;
#pragma unroll
    for (int mf = 0; mf < 2; mf++)
#pragma unroll
        for (int nf = 0; nf < 2; nf++) {
            int row = t0 + wm + mf * 16 + rl;
            int col = f0 + wn + nf * 8 + cp;
            float* b0 = g_hs + ((size_t)s * NT + row) * SFF + col;
            *(float2*)b0 = make_float2(silu_f(ag[mf][nf][0]) * au[mf][nf][0],
                                       silu_f(ag[mf][nf][1]) * au[mf][nf][1]);
            *(float2*)(b0 + (size_t)8 * SFF) =
                       make_float2(silu_f(ag[mf][nf][2]) * au[mf][nf][2],
                                   silu_f(ag[mf][nf][3]) * au[mf][nf][3]);
        }
}

// ---- expert gate/up (gathered rows) + SwiGLU ------------------------------
__global__ __launch_bounds__(512)
void k_ex_gu(const float* __restrict__ x,
             const float* __restrict__ gw, const float* __restrict__ uw)
{
    const int e = blockIdx.x;
    const int t0 = blockIdx.y * 128, f0 = blockIdx.z * 64;
    if (t0 >= g_counts[e]) return;

    extern __shared__ char sm[];
    __shared__ int toks[128];
    const int tid = threadIdx.x, wid = tid >> 5, lane = tid & 31;
    const int wm = (wid >> 2) * 32, wn = (wid & 3) * 16;
    uint32_t smb = smem_u32(sm);

    if (tid < 128) toks[tid] = g_tok_table[e * CAP + t0 + tid];
    __syncthreads();

    const uint32_t aCol = (lane >> 4) * 16;
    const uint32_t offA0 = (uint32_t)(wm + (lane & 15)) * SST_B + aCol;
    const uint32_t offA1 = offA0 + 16 * SST_B;
    const uint32_t offB  = (uint32_t)(wn + ((lane >> 4) << 3) + (lane & 7)) * SST_B
                         + ((lane >> 3) & 1) * 16;

    const float* Gsrc = gw + ((size_t)e * FF + f0) * DM;
    const float* Usrc = uw + ((size_t)e * FF + f0) * DM;

    float ag[2][2][4] = {}, au[2][2][4] = {};
    float4 pa[4], pg[2], pu[2];

#pragma unroll
    for (int ii = 0; ii < 4; ii++) {
        int i = tid + ii * 512, r = i >> 4, c4 = (i & 15) << 2;
        pa[ii] = *(const float4*)(x + (size_t)toks[r] * DM + c4);
    }
#pragma unroll
    for (int ii = 0; ii < 2; ii++) {
        int i = tid + ii * 512, r = i >> 4, c4 = (i & 15) << 2;
        pg[ii] = *(const float4*)(Gsrc + (size_t)r * DM + c4);
        pu[ii] = *(const float4*)(Usrc + (size_t)r * DM + c4);
    }
    {
        char* A  = sm;             char* Bgh = sm + ABYTES;
        char* Bgl = Bgh + BBYTES;  char* Buh = Bgl + BBYTES; char* Bul = Buh + BBYTES;
#pragma unroll
        for (int ii = 0; ii < 4; ii++) {
            int i = tid + ii * 512, r = i >> 4, c4 = (i & 15) << 2;
            cvt_storeA(pa[ii], A, r, c4);
        }
#pragma unroll
        for (int ii = 0; ii < 2; ii++) {
            int i = tid + ii * 512, r = i >> 4, c4 = (i & 15) << 2;
            cvt_storeB(pg[ii], Bgh, Bgl, r, c4);
            cvt_storeB(pu[ii], Buh, Bul, r, c4);
        }
    }
    __syncthreads();

    for (int it = 0; it < DM / 64; it++) {
        if (it + 1 < DM / 64) {
            int kt = (it + 1) * 64;
#pragma unroll
            for (int ii = 0; ii < 4; ii++) {
                int i = tid + ii * 512, r = i >> 4, c4 = (i & 15) << 2;
                pa[ii] = *(const float4*)(x + (size_t)toks[r] * DM + kt + c4);
            }
#pragma unroll
            for (int ii = 0; ii < 2; ii++) {
                int i = tid + ii * 512, r = i >> 4, c4 = (i & 15) << 2;
                pg[ii] = *(const float4*)(Gsrc + (size_t)r * DM + kt + c4);
                pu[ii] = *(const float4*)(Usrc + (size_t)r * DM + kt + c4);
            }
        }
        gu_compute(smb + (it & 1) * GU_STG, offA0, offA1, offB, ag, au);
        if (it + 1 < DM / 64) {
            char* base = sm + ((it + 1) & 1) * GU_STG;
            char* A  = base;            char* Bgh = base + ABYTES;
            char* Bgl = Bgh + BBYTES;   char* Buh = Bgl + BBYTES; char* Bul = Buh + BBYTES;
#pragma unroll
            for (int ii = 0; ii < 4; ii++) {
                int i = tid + ii * 512, r = i >> 4, c4 = (i & 15) << 2;
                cvt_storeA(pa[ii], A, r, c4);
            }
#pragma unroll
            for (int ii = 0; ii < 2; ii++) {
                int i = tid + ii * 512, r = i >> 4, c4 = (i & 15) << 2;
                cvt_storeB(pg[ii], Bgh, Bgl, r, c4);
                cvt_storeB(pu[ii], Buh, Bul, r, c4);
            }
        }
        __syncthreads();
    }

    const int rl = lane >> 2, cp = (lane & 3) * 2;
#pragma unroll
    for (int mf = 0; mf < 2; mf++)
#pragma unroll
        for (int nf = 0; nf < 2; nf++) {
            int row = t0 + wm + mf * 16 + rl;
            int col = f0 + wn + nf * 8 + cp;
            float* b0 = g_h + ((size_t)e * CAP + row) * FF + col;
            *(float2*)b0 = make_float2(silu_f(ag[mf][nf][0]) * au[mf][nf][0],
                                       silu_f(ag[mf][nf][1]) * au[mf][nf][1]);
            *(float2*)(b0 + (size_t)8 * FF) =
                       make_float2(silu_f(ag[mf][nf][2]) * au[mf][nf][2],
                                   silu_f(ag[mf][nf][3]) * au[mf][nf][3]);
        }
}

// ---- shared down: out = sum_s hs_s @ sd_s^T (initializes out) -------------
__global__ __launch_bounds__(512)
void k_sh_dn(const float* __restrict__ sdw, float* __restrict__ out)
{
    extern __shared__ char sm[];
    const int tid = threadIdx.x, wid = tid >> 5, lane = tid & 31;
    const int t0 = blockIdx.x * 128, d0 = blockIdx.y * 64;
    const int wm = (wid >> 2) * 32, wn = (wid & 3) * 16;
    uint32_t smb = smem_u32(sm);

    const uint32_t aCol = (lane >> 4) * 16;
    const uint32_t offA0 = (uint32_t)(wm + (lane & 15)) * SST_B + aCol;
    const uint32_t offA1 = offA0 + 16 * SST_B;
    const uint32_t offB  = (uint32_t)(wn + ((lane >> 4) << 3) + (lane & 7)) * SST_B
                         + ((lane >> 3) & 1) * 16;

    float ac[2][2][4] = {};
    float4 pa[4], pb[2];

#pragma unroll
    for (int ii = 0; ii < 4; ii++) {
        int i = tid + ii * 512, r = i >> 4, c4 = (i & 15) << 2;
        pa[ii] = *(const float4*)(g_hs + ((size_t)t0 + r) * SFF + c4);
    }
#pragma unroll
    for (int ii = 0; ii < 2; ii++) {
        int i = tid + ii * 512, r = i >> 4, c4 = (i & 15) << 2;
        pb[ii] = *(const float4*)(sdw + ((size_t)d0 + r) * SFF + c4);
    }
    {
        char* A = sm; char* Bh = sm + ABYTES; char* Bl = Bh + BBYTES;
#pragma unroll
        for (int ii = 0; ii < 4; ii++) {
            int i = tid + ii * 512, r = i >> 4, c4 = (i & 15) << 2;
            cvt_storeA(pa[ii], A, r, c4);
        }
#pragma unroll
        for (int ii = 0; ii < 2; ii++) {
            int i = tid + ii * 512, r = i >> 4, c4 = (i & 15) << 2;
            cvt_storeB(pb[ii], Bh, Bl, r, c4);
        }
    }
    __syncthreads();

    for (int it = 0; it < 64; it++) {
        if (it + 1 < 64) {
            int s  = (it + 1) >> 5;
            int kt = ((it + 1) & 31) * 64;
#pragma unroll
            for (int ii = 0; ii < 4; ii++) {
                int i = tid + ii * 512, r = i >> 4, c4 = (i & 15) << 2;
                pa[ii] = *(const float4*)(g_hs + ((size_t)s * NT + t0 + r) * SFF + kt + c4);
            }
#pragma unroll
            for (int ii = 0; ii < 2; ii++) {
                int i = tid + ii * 512, r = i >> 4, c4 = (i & 15) << 2;
                pb[ii] = *(const float4*)(sdw + ((size_t)s * DM + d0 + r) * SFF + kt + c4);
            }
        }
        dn_compute(smb + (it & 1) * DN_STG, offA0, offA1, offB, ac);
        if (it + 1 < 64) {
            char* base = sm + ((it + 1) & 1) * DN_STG;
            char* A = base; char* Bh = base + ABYTES; char* Bl = Bh + BBYTES;
#pragma unroll
            for (int ii = 0; ii < 4; ii++) {
                int i = tid + ii * 512, r = i >> 4, c4 = (i & 15) << 2;
                cvt_storeA(pa[ii], A, r, c4);
            }
#pragma unroll
            for (int ii = 0; ii < 2; ii++) {
                int i = tid + ii * 512, r = i >> 4, c4 = (i & 15) << 2;
                cvt_storeB(pb[ii], Bh, Bl, r, c4);
            }
        }
        __syncthreads();
    }

    const int rl = lane >> 2, cp = (lane & 3) * 2;
#pragma unroll
    for (int mf = 0; mf < 2; mf++)
#pragma unroll
        for (int nf = 0; nf < 2; nf++) {
            int row = t0 + wm + mf * 16 + rl;
            int col = d0 + wn + nf * 8 + cp;
            float* b0 = out + (size_t)row * DM + col;
            *(float2*)b0 = make_float2(ac[mf][nf][0], ac[mf][nf][1]);
            *(float2*)(b0 + (size_t)8 * DM) = make_float2(ac[mf][nf][2], ac[mf][nf][3]);
        }
}

// ---- expert down: y = h @ down^T (plain stores to g_y) --------------------
__global__ __launch_bounds__(512)
void k_ex_dn(const float* __restrict__ dw)
{
    const int e = blockIdx.x;
    const int t0 = blockIdx.y * 128, d0 = blockIdx.z * 64;
    if (t0 >= g_counts[e]) return;

    extern __shared__ char sm[];
    const int tid = threadIdx.x, wid = tid >> 5, lane = tid & 31;
    const int wm = (wid >> 2) * 32, wn = (wid & 3) * 16;
    uint32_t smb = smem_u32(sm);

    const uint32_t aCol = (lane >> 4) * 16;
    const uint32_t offA0 = (uint32_t)(wm + (lane & 15)) * SST_B + aCol;
    const uint32_t offA1 = offA0 + 16 * SST_B;
    const uint32_t offB  = (uint32_t)(wn + ((lane >> 4) << 3) + (lane & 7)) * SST_B
                         + ((lane >> 3) & 1) * 16;

    const float* Asrc = g_h + ((size_t)e * CAP + t0) * FF;
    const float* Bsrc = dw  + ((size_t)e * DM + d0) * FF;

    float ac[2][2][4] = {};
    float4 pa[4], pb[2];

#pragma unroll
    for (int ii = 0; ii < 4; ii++) {
        int i = tid + ii * 512, r = i >> 4, c4 = (i & 15) << 2;
        pa[ii] = *(const float4*)(Asrc + (size_t)r * FF + c4);
    }
#pragma unroll
    for (int ii = 0; ii < 2; ii++) {
        int i = tid + ii * 512, r = i >> 4, c4 = (i & 15) << 2;
        pb[ii] = *(const float4*)(Bsrc + (size_t)r * FF + c4);
    }
    {
        char* A = sm; char* Bh = sm + ABYTES; char* Bl = Bh + BBYTES;
#pragma unroll
        for (int ii = 0; ii < 4; ii++) {
            int i = tid + ii * 512, r = i >> 4, c4 = (i & 15) << 2;
            cvt_storeA(pa[ii], A, r, c4);
        }
#pragma unroll
        for (int ii = 0; ii < 2; ii++) {
            int i = tid + ii * 512, r = i >> 4, c4 = (i & 15) << 2;
            cvt_storeB(pb[ii], Bh, Bl, r, c4);
        }
    }
    __syncthreads();

    for (int it = 0; it < FF / 64; it++) {
        if (it + 1 < FF / 64) {
            int kt = (it + 1) * 64;
#pragma unroll
            for (int ii = 0; ii < 4; ii++) {
                int i = tid + ii * 512, r = i >> 4, c4 = (i & 15) << 2;
                pa[ii] = *(const float4*)(Asrc + (size_t)r * FF + kt + c4);
            }
#pragma unroll
            for (int ii = 0; ii < 2; ii++) {
                int i = tid + ii * 512, r = i >> 4, c4 = (i & 15) << 2;
                pb[ii] = *(const float4*)(Bsrc + (size_t)r * FF + kt + c4);
            }
        }
        dn_compute(smb + (it & 1) * DN_STG, offA0, offA1, offB, ac);
        if (it + 1 < FF / 64) {
            char* base = sm + ((it + 1) & 1) * DN_STG;
            char* A = base; char* Bh = base + ABYTES; char* Bl = Bh + BBYTES;
#pragma unroll
            for (int ii = 0; ii < 4; ii++) {
                int i = tid + ii * 512, r = i >> 4, c4 = (i & 15) << 2;
                cvt_storeA(pa[ii], A, r, c4);
            }
#pragma unroll
            for (int ii = 0; ii < 2; ii++) {
                int i = tid + ii * 512, r = i >> 4, c4 = (i & 15) << 2;
                cvt_storeB(pb[ii], Bh, Bl, r, c4);
            }
        }
        __syncthreads();
    }

    const int rl = lane >> 2, cp = (lane & 3) * 2;
#pragma unroll
    for (int mf = 0; mf < 2; mf++)
#pragma unroll
        for (int nf = 0; nf < 2; nf++) {
            int row = t0 + wm + mf * 16 + rl;
            int col = d0 + wn + nf * 8 + cp;
            float* b0 = g_y + ((size_t)e * CAP + row) * DM + col;
            *(float2*)b0 = make_float2(ac[mf][nf][0], ac[mf][nf][1]);
            *(float2*)(b0 + (size_t)8 * DM) = make_float2(ac[mf][nf][2], ac[mf][nf][3]);
        }
}

// ===========================================================================
// Combine
// ===========================================================================
__global__ __launch_bounds__(256)
void k_combine(float* __restrict__ out)
{
    const int n = blockIdx.x, tid = threadIdx.x;
    int sl[TOPK]; float w[TOPK];
#pragma unroll
    for (int r = 0; r < TOPK; r++) {
        sl[r] = g_pair_slot[n * TOPK + r];
        w[r]  = g_topk_w[n * TOPK + r];
    }
    float* orow = out + (size_t)n * DM;
#pragma unroll
    for (int d = tid * 4; d < DM; d += 1024) {
        float4 acc = *(float4*)(orow + d);
#pragma unroll
        for (int r = 0; r < TOPK; r++) {
            if (sl[r] >= 0) {
                float4 yv = *(const float4*)(g_y + (size_t)sl[r] * DM + d);
                acc.x += w[r] * yv.x; acc.y += w[r] * yv.y;
                acc.z += w[r] * yv.z; acc.w += w[r] * yv.w;
            }
        }
        *(float4*)(orow + d) = acc;
    }
}

// ===========================================================================
// Launch
// ===========================================================================
extern "C" void kernel_launch(void* const* d_in, const int* in_sizes, int n_in,
                              void* d_out, int out_size)
{
    const float* x      = (const float*)d_in[0];
    const float* rw     = (const float*)d_in[1];
    const float* rbias  = (const float*)d_in[2];
    const float* gate_w = (const float*)d_in[3];
    const float* up_w   = (const float*)d_in[4];
    const float* down_w = (const float*)d_in[5];
    const float* sg_w   = (const float*)d_in[6];
    const float* su_w   = (const float*)d_in[7];
    const float* sd_w   = (const float*)d_in[8];
    float* out = (float*)d_out;

    cudaFuncSetAttribute(k_sh_gu, cudaFuncAttributeMaxDynamicSharedMemorySize, GU_SMEM);
    cudaFuncSetAttribute(k_ex_gu, cudaFuncAttributeMaxDynamicSharedMemorySize, GU_SMEM);
    cudaFuncSetAttribute(k_sh_dn, cudaFuncAttributeMaxDynamicSharedMemorySize, DN_SMEM);
    cudaFuncSetAttribute(k_ex_dn, cudaFuncAttributeMaxDynamicSharedMemorySize, DN_SMEM);

    k_router_logits<<<NT / RBM, 256>>>(x, rw);
    k_topk<<<NT, 32>>>(rbias);
    k_dispatch<<<NE, 256>>>();

    k_ex_gu<<<dim3(NE, CAP / 128, FF / 64), 512, GU_SMEM>>>(x, gate_w, up_w);
    k_sh_gu<<<dim3(NT / 128, SFF / 64, NS), 512, GU_SMEM>>>(x, sg_w, su_w);

    k_sh_dn<<<dim3(NT / 128, DM / 64), 512, DN_SMEM>>>(sd_w, out);
    k_ex_dn<<<dim3(NE, CAP / 128, DM / 64), 512, DN_SMEM>>>(down_w);

    k_combine<<<NT, 256>>>(out);
}

// round 5
// speedup vs baseline: 3.7327x; 1.0952x over previous
#include <cuda_runtime.h>
#include <cuda_fp16.h>
#include <math.h>
#include <stdint.h>

// ---------------------------------------------------------------------------
// Problem constants
// ---------------------------------------------------------------------------
#define NT   2048
#define DM   2048
#define NE   64
#define TOPK 4
#define FF   512
#define NS   2
#define SFF  2048
#define CAP  256
#define NP   (NT * TOPK)

// ---------------------------------------------------------------------------
// Device scratch
// ---------------------------------------------------------------------------
__device__ float  g_logits[NT * NE];
__device__ int    g_topk_idx[NP];
__device__ float  g_topk_w[NP];
__device__ int    g_pair_slot[NP];
__device__ int    g_tok_table[NE * CAP];
__device__ int    g_counts[NE];
__device__ __half g_xh[NT * DM];            // x in fp16 (8 MB)
__device__ __half g_h [NE * CAP * FF];      // expert hidden fp16 (16.8 MB)
__device__ __half g_hs[NS * NT * SFF];      // shared hidden fp16 (16.8 MB)
__device__ float  g_y [(size_t)NE * CAP * DM]; // expert down out fp32 (134 MB)

// ---------------------------------------------------------------------------
// Helpers
// ---------------------------------------------------------------------------
__device__ __forceinline__ uint32_t smem_u32(const void* p) {
    uint32_t a;
    asm("{ .reg .u64 t; cvta.to.shared.u64 t, %1; cvt.u32.u64 %0, t; }" : "=r"(a) : "l"(p));
    return a;
}
__device__ __forceinline__ void ldsm4(uint32_t r[4], uint32_t a) {
    asm volatile("ldmatrix.sync.aligned.m8n8.x4.shared.b16 {%0,%1,%2,%3}, [%4];"
        : "=r"(r[0]), "=r"(r[1]), "=r"(r[2]), "=r"(r[3]) : "r"(a));
}
__device__ __forceinline__ void mma_f16(float c[4], const uint32_t a[4], const uint32_t b[2]) {
    asm volatile("mma.sync.aligned.m16n8k16.row.col.f32.f16.f16.f32 "
        "{%0,%1,%2,%3}, {%4,%5,%6,%7}, {%8,%9}, {%0,%1,%2,%3};"
        : "+f"(c[0]), "+f"(c[1]), "+f"(c[2]), "+f"(c[3])
        : "r"(a[0]), "r"(a[1]), "r"(a[2]), "r"(a[3]), "r"(b[0]), "r"(b[1]));
}
__device__ __forceinline__ uint32_t h2u(__half2 h) { return *(uint32_t*)&h; }

// SMEM row stride: 72 halves = 144 B (16B aligned; conflict-free ldmatrix)
#define SST_B 144

// B: fp32 -> fp16 hi + lo residual
__device__ __forceinline__ void cvt_storeB(float4 v, char* hi, char* lo, int r, int c4) {
    __half2 h0 = __floats2half2_rn(v.x, v.y);
    __half2 h1 = __floats2half2_rn(v.z, v.w);
    float2 f0 = __half22float2(h0), f1 = __half22float2(h1);
    __half2 l0 = __floats2half2_rn(v.x - f0.x, v.y - f0.y);
    __half2 l1 = __floats2half2_rn(v.z - f1.x, v.w - f1.y);
    uint32_t off = (uint32_t)(r * SST_B + c4 * 2);
    *(uint2*)(hi + off) = make_uint2(h2u(h0), h2u(h1));
    *(uint2*)(lo + off) = make_uint2(h2u(l0), h2u(l1));
}
// A: fp16 copy (8 halves)
__device__ __forceinline__ void copy_storeA(uint4 v, char* dst, int r, int c8) {
    *(uint4*)(dst + (uint32_t)(r * SST_B + c8 * 2)) = v;
}
__device__ __forceinline__ float silu_f(float g) { return g / (1.f + expf(-g)); }

// Stage layouts
#define ABYTES 18432                     // 128 rows * 144B
#define BBYTES  9216                     // 64 rows * 144B
#define GU_STG (ABYTES + 4 * BBYTES)     // A | Bgh | Bgl | Buh | Bul = 55296
#define GU_SMEM (2 * GU_STG)             // 110592
#define DN_STG (3 * ABYTES)              // A | Bh(128) | Bl(128) = 55296
#define DN_SMEM (2 * DN_STG)             // 110592

// ===========================================================================
// 0) x -> fp16
// ===========================================================================
__global__ __launch_bounds__(256)
void k_cvt_x(const float* __restrict__ x)
{
    int i = (blockIdx.x * 256 + threadIdx.x) * 4;
    float4 v = *(const float4*)(x + i);
    __half2 h0 = __floats2half2_rn(v.x, v.y);
    __half2 h1 = __floats2half2_rn(v.z, v.w);
    *(uint2*)(g_xh + i) = make_uint2(h2u(h0), h2u(h1));
}

// ===========================================================================
// 1) Router logits (SIMT fp32)
// ===========================================================================
#define RBM 64
#define RBK 16
__global__ __launch_bounds__(256)
void k_router_logits(const float* __restrict__ x, const float* __restrict__ rw)
{
    __shared__ __align__(16) float As[RBK][RBM];
    __shared__ __align__(16) float Bs[RBK][RBM];
    const int tid = threadIdx.x;
    const int t0  = blockIdx.x * RBM;
    const int lr  = tid >> 2, lk = (tid & 3) * 4;
    const int ty4 = (tid >> 4) * 4, tx4 = (tid & 15) * 4;
    float acc[4][4];
#pragma unroll
    for (int i = 0; i < 4; i++)
#pragma unroll
        for (int j = 0; j < 4; j++) acc[i][j] = 0.f;
    for (int kt = 0; kt < DM; kt += RBK) {
        float4 a = *(const float4*)(x + (size_t)(t0 + lr) * DM + kt + lk);
        As[lk+0][lr] = a.x; As[lk+1][lr] = a.y; As[lk+2][lr] = a.z; As[lk+3][lr] = a.w;
        float4 b = *(const float4*)(rw + (size_t)lr * DM + kt + lk);
        Bs[lk+0][lr] = b.x; Bs[lk+1][lr] = b.y; Bs[lk+2][lr] = b.z; Bs[lk+3][lr] = b.w;
        __syncthreads();
#pragma unroll
        for (int k = 0; k < RBK; k++) {
            float4 av = *(const float4*)&As[k][ty4];
            float4 bv = *(const float4*)&Bs[k][tx4];
            float a4[4] = {av.x, av.y, av.z, av.w};
            float b4[4] = {bv.x, bv.y, bv.z, bv.w};
#pragma unroll
            for (int i = 0; i < 4; i++)
#pragma unroll
                for (int j = 0; j < 4; j++) acc[i][j] += a4[i] * b4[j];
        }
        __syncthreads();
    }
#pragma unroll
    for (int i = 0; i < 4; i++)
#pragma unroll
        for (int j = 0; j < 4; j++)
            g_logits[(size_t)(t0 + ty4 + i) * NE + tx4 + j] = acc[i][j];
}

// ===========================================================================
// 2) Top-k (1 warp / token)
// ===========================================================================
__global__ void k_topk(const float* __restrict__ bias)
{
    const int n = blockIdx.x, lane = threadIdx.x;
    float l0 = g_logits[n * NE + lane];
    float l1 = g_logits[n * NE + 32 + lane];
    float s0 = l0 + bias[lane];
    float s1 = l1 + bias[32 + lane];
    int ch_idx[TOPK]; float ch_l[TOPK];
#pragma unroll
    for (int r = 0; r < TOPK; r++) {
        float v = s0; int idx = lane;
        if (s1 > v) { v = s1; idx = lane + 32; }
#pragma unroll
        for (int off = 16; off > 0; off >>= 1) {
            float ov = __shfl_xor_sync(0xffffffffu, v, off);
            int   oi = __shfl_xor_sync(0xffffffffu, idx, off);
            if (ov > v || (ov == v && oi < idx)) { v = ov; idx = oi; }
        }
        int owner = (idx < 32) ? idx : (idx - 32);
        float rawA = __shfl_sync(0xffffffffu, l0, owner);
        float rawB = __shfl_sync(0xffffffffu, l1, owner);
        ch_idx[r] = idx;
        ch_l[r]   = (idx < 32) ? rawA : rawB;
        if (lane == owner) { if (idx < 32) s0 = -INFINITY; else s1 = -INFINITY; }
    }
    if (lane == 0) {
        float m = ch_l[0];
#pragma unroll
        for (int r = 1; r < TOPK; r++) m = fmaxf(m, ch_l[r]);
        float w[TOPK], sum = 0.f;
#pragma unroll
        for (int r = 0; r < TOPK; r++) { w[r] = expf(ch_l[r] - m); sum += w[r]; }
        float inv = 1.f / sum;
#pragma unroll
        for (int r = 0; r < TOPK; r++) {
            g_topk_idx[n * TOPK + r] = ch_idx[r];
            g_topk_w[n * TOPK + r]   = w[r] * inv;
        }
    }
}

// ===========================================================================
// 3) Dispatch
// ===========================================================================
__global__ __launch_bounds__(256)
void k_dispatch()
{
    const int e = blockIdx.x, tid = threadIdx.x;
    const int wid = tid >> 5, lane = tid & 31;
    __shared__ int warp_tot[8];
    int base = 0;
    for (int p0 = 0; p0 < NP; p0 += 256) {
        int p = p0 + tid;
        bool pr = (g_topk_idx[p] == e);
        unsigned b = __ballot_sync(0xffffffffu, pr);
        int wp = __popc(b & ((1u << lane) - 1u));
        if (lane == 0) warp_tot[wid] = __popc(b);
        __syncthreads();
        int off = base;
        for (int w = 0; w < wid; w++) off += warp_tot[w];
        int slot = off + wp;
        if (pr) {
            if (slot < CAP) {
                g_tok_table[e * CAP + slot] = p >> 2;
                g_pair_slot[p] = e * CAP + slot;
            } else {
                g_pair_slot[p] = -1;
            }
        }
        int tot = 0;
        for (int w = 0; w < 8; w++) tot += warp_tot[w];
        base += tot;
        __syncthreads();
    }
    int cnt = (base < CAP) ? base : CAP;
    if (tid == 0) g_counts[e] = cnt;
    for (int i = cnt + tid; i < CAP; i += 256)
        g_tok_table[e * CAP + i] = 0;
}

// ===========================================================================
// GEMM compute cores
// ===========================================================================
// gate/up: CTA 128Mx64N (per matrix), 16 warps 4Mx4N, warp tile 32x16
__device__ __forceinline__ void gu_compute(
    uint32_t ub, uint32_t offA0, uint32_t offA1, uint32_t offB,
    float ag[2][2][4], float au[2][2][4])
{
    const uint32_t uA = ub, uBgh = ub + ABYTES, uBgl = uBgh + BBYTES;
    const uint32_t uBuh = uBgl + BBYTES, uBul = uBuh + BBYTES;
#pragma unroll
    for (int ks = 0; ks < 4; ks++) {
        uint32_t kb = ks * 32;
        uint32_t ah[2][4], bgh[4], bgl[4], buh[4], bul[4];
        ldsm4(ah[0], uA + offA0 + kb); ldsm4(ah[1], uA + offA1 + kb);
        ldsm4(bgh, uBgh + offB + kb);  ldsm4(bgl, uBgl + offB + kb);
        ldsm4(buh, uBuh + offB + kb);  ldsm4(bul, uBul + offB + kb);
#pragma unroll
        for (int mf = 0; mf < 2; mf++)
#pragma unroll
            for (int nf = 0; nf < 2; nf++) {
                mma_f16(ag[mf][nf], ah[mf], &bgh[nf * 2]);
                mma_f16(ag[mf][nf], ah[mf], &bgl[nf * 2]);
                mma_f16(au[mf][nf], ah[mf], &buh[nf * 2]);
                mma_f16(au[mf][nf], ah[mf], &bul[nf * 2]);
            }
    }
}

// down: CTA 128Mx128N, 16 warps 4Mx4N, warp tile 32x32
__device__ __forceinline__ void dn_compute(
    uint32_t ub, uint32_t offA0, uint32_t offA1, uint32_t offB,
    float ac[2][4][4])
{
    const uint32_t uA = ub, uBh = ub + ABYTES, uBl = ub + 2 * ABYTES;
#pragma unroll
    for (int ks = 0; ks < 4; ks++) {
        uint32_t kb = ks * 32;
        uint32_t ah[2][4], bh01[4], bh23[4], bl01[4], bl23[4];
        ldsm4(ah[0], uA + offA0 + kb); ldsm4(ah[1], uA + offA1 + kb);
        ldsm4(bh01, uBh + offB + kb);  ldsm4(bh23, uBh + offB + 16 * SST_B + kb);
        ldsm4(bl01, uBl + offB + kb);  ldsm4(bl23, uBl + offB + 16 * SST_B + kb);
#pragma unroll
        for (int mf = 0; mf < 2; mf++) {
            mma_f16(ac[mf][0], ah[mf], &bh01[0]);
            mma_f16(ac[mf][0], ah[mf], &bl01[0]);
            mma_f16(ac[mf][1], ah[mf], &bh01[2]);
            mma_f16(ac[mf][1], ah[mf], &bl01[2]);
            mma_f16(ac[mf][2], ah[mf], &bh23[0]);
            mma_f16(ac[mf][2], ah[mf], &bl23[0]);
            mma_f16(ac[mf][3], ah[mf], &bh23[2]);
            mma_f16(ac[mf][3], ah[mf], &bl23[2]);
        }
    }
}

// ---- shared experts gate/up + SwiGLU --------------------------------------
__global__ __launch_bounds__(512)
void k_sh_gu(const float* __restrict__ sgw, const float* __restrict__ suw)
{
    extern __shared__ char sm[];
    const int tid = threadIdx.x, wid = tid >> 5, lane = tid & 31;
    const int t0 = blockIdx.x * 128, f0 = blockIdx.y * 64, s = blockIdx.z;
    const int wm = (wid >> 2) * 32, wn = (wid & 3) * 16;
    uint32_t smb = smem_u32(sm);

    const uint32_t aCol = (lane >> 4) * 16;
    const uint32_t offA0 = (uint32_t)(wm + (lane & 15)) * SST_B + aCol;
    const uint32_t offA1 = offA0 + 16 * SST_B;
    const uint32_t offB  = (uint32_t)(wn + ((lane >> 4) << 3) + (lane & 7)) * SST_B
                         + ((lane >> 3) & 1) * 16;

    const __half* Asrc = g_xh + (size_t)t0 * DM;
    const float*  Gsrc = sgw + ((size_t)s * SFF + f0) * DM;
    const float*  Usrc = suw + ((size_t)s * SFF + f0) * DM;

    float ag[2][2][4] = {}, au[2][2][4] = {};
    uint4  pa[2];
    float4 pg[2], pu[2];

#pragma unroll
    for (int ii = 0; ii < 2; ii++) {
        int i = tid + ii * 512;
        int ra = i >> 3, c8 = (i & 7) << 3;
        pa[ii] = *(const uint4*)(Asrc + (size_t)ra * DM + c8);
        int rb = i >> 4, c4 = (i & 15) << 2;
        pg[ii] = *(const float4*)(Gsrc + (size_t)rb * DM + c4);
        pu[ii] = *(const float4*)(Usrc + (size_t)rb * DM + c4);
    }
    {
        char* A = sm; char* Bgh = sm + ABYTES; char* Bgl = Bgh + BBYTES;
        char* Buh = Bgl + BBYTES; char* Bul = Buh + BBYTES;
#pragma unroll
        for (int ii = 0; ii < 2; ii++) {
            int i = tid + ii * 512;
            copy_storeA(pa[ii], A, i >> 3, (i & 7) << 3);
            cvt_storeB(pg[ii], Bgh, Bgl, i >> 4, (i & 15) << 2);
            cvt_storeB(pu[ii], Buh, Bul, i >> 4, (i & 15) << 2);
        }
    }
    __syncthreads();

    for (int it = 0; it < DM / 64; it++) {
        if (it + 1 < DM / 64) {
            int kt = (it + 1) * 64;
#pragma unroll
            for (int ii = 0; ii < 2; ii++) {
                int i = tid + ii * 512;
                int ra = i >> 3, c8 = (i & 7) << 3;
                pa[ii] = *(const uint4*)(Asrc + (size_t)ra * DM + kt + c8);
                int rb = i >> 4, c4 = (i & 15) << 2;
                pg[ii] = *(const float4*)(Gsrc + (size_t)rb * DM + kt + c4);
                pu[ii] = *(const float4*)(Usrc + (size_t)rb * DM + kt + c4);
            }
        }
        gu_compute(smb + (it & 1) * GU_STG, offA0, offA1, offB, ag, au);
        if (it + 1 < DM / 64) {
            char* base = sm + ((it + 1) & 1) * GU_STG;
            char* A = base; char* Bgh = base + ABYTES; char* Bgl = Bgh + BBYTES;
            char* Buh = Bgl + BBYTES; char* Bul = Buh + BBYTES;
#pragma unroll
            for (int ii = 0; ii < 2; ii++) {
                int i = tid + ii * 512;
                copy_storeA(pa[ii], A, i >> 3, (i & 7) << 3);
                cvt_storeB(pg[ii], Bgh, Bgl, i >> 4, (i & 15) << 2);
                cvt_storeB(pu[ii], Buh, Bul, i >> 4, (i & 15) << 2);
            }
        }
        __syncthreads();
    }

    const int rl = lane >> 2, cp = (lane & 3) * 2;
#pragma unroll
    for (int mf = 0; mf < 2; mf++)
#pragma unroll
        for (int nf = 0; nf < 2; nf++) {
            int row = t0 + wm + mf * 16 + rl;
            int col = f0 + wn + nf * 8 + cp;
            __half* b0 = g_hs + ((size_t)s * NT + row) * SFF + col;
            *(__half2*)b0 = __floats2half2_rn(silu_f(ag[mf][nf][0]) * au[mf][nf][0],
                                              silu_f(ag[mf][nf][1]) * au[mf][nf][1]);
            *(__half2*)(b0 + (size_t)8 * SFF) =
                            __floats2half2_rn(silu_f(ag[mf][nf][2]) * au[mf][nf][2],
                                              silu_f(ag[mf][nf][3]) * au[mf][nf][3]);
        }
}

// ---- expert gate/up (gathered rows) + SwiGLU ------------------------------
__global__ __launch_bounds__(512)
void k_ex_gu(const float* __restrict__ gw, const float* __restrict__ uw)
{
    const int e = blockIdx.x;
    const int t0 = blockIdx.y * 128, f0 = blockIdx.z * 64;
    if (t0 >= g_counts[e]) return;

    extern __shared__ char sm[];
    __shared__ int toks[128];
    const int tid = threadIdx.x, wid = tid >> 5, lane = tid & 31;
    const int wm = (wid >> 2) * 32, wn = (wid & 3) * 16;
    uint32_t smb = smem_u32(sm);

    if (tid < 128) toks[tid] = g_tok_table[e * CAP + t0 + tid];
    __syncthreads();

    const uint32_t aCol = (lane >> 4) * 16;
    const uint32_t offA0 = (uint32_t)(wm + (lane & 15)) * SST_B + aCol;
    const uint32_t offA1 = offA0 + 16 * SST_B;
    const uint32_t offB  = (uint32_t)(wn + ((lane >> 4) << 3) + (lane & 7)) * SST_B
                         + ((lane >> 3) & 1) * 16;

    const float* Gsrc = gw + ((size_t)e * FF + f0) * DM;
    const float* Usrc = uw + ((size_t)e * FF + f0) * DM;

    float ag[2][2][4] = {}, au[2][2][4] = {};
    uint4  pa[2];
    float4 pg[2], pu[2];

#pragma unroll
    for (int ii = 0; ii < 2; ii++) {
        int i = tid + ii * 512;
        int ra = i >> 3, c8 = (i & 7) << 3;
        pa[ii] = *(const uint4*)(g_xh + (size_t)toks[ra] * DM + c8);
        int rb = i >> 4, c4 = (i & 15) << 2;
        pg[ii] = *(const float4*)(Gsrc + (size_t)rb * DM + c4);
        pu[ii] = *(const float4*)(Usrc + (size_t)rb * DM + c4);
    }
    {
        char* A = sm; char* Bgh = sm + ABYTES; char* Bgl = Bgh + BBYTES;
        char* Buh = Bgl + BBYTES; char* Bul = Buh + BBYTES;
#pragma unroll
        for (int ii = 0; ii < 2; ii++) {
            int i = tid + ii * 512;
            copy_storeA(pa[ii], A, i >> 3, (i & 7) << 3);
            cvt_storeB(pg[ii], Bgh, Bgl, i >> 4, (i & 15) << 2);
            cvt_storeB(pu[ii], Buh, Bul, i >> 4, (i & 15) << 2);
        }
    }
    __syncthreads();

    for (int it = 0; it < DM / 64; it++) {
        if (it + 1 < DM / 64) {
            int kt = (it + 1) * 64;
#pragma unroll
            for (int ii = 0; ii < 2; ii++) {
                int i = tid + ii * 512;
                int ra = i >> 3, c8 = (i & 7) << 3;
                pa[ii] = *(const uint4*)(g_xh + (size_t)toks[ra] * DM + kt + c8);
                int rb = i >> 4, c4 = (i & 15) << 2;
                pg[ii] = *(const float4*)(Gsrc + (size_t)rb * DM + kt + c4);
                pu[ii] = *(const float4*)(Usrc + (size_t)rb * DM + kt + c4);
            }
        }
        gu_compute(smb + (it & 1) * GU_STG, offA0, offA1, offB, ag, au);
        if (it + 1 < DM / 64) {
            char* base = sm + ((it + 1) & 1) * GU_STG;
            char* A = base; char* Bgh = base + ABYTES; char* Bgl = Bgh + BBYTES;
            char* Buh = Bgl + BBYTES; char* Bul = Buh + BBYTES;
#pragma unroll
            for (int ii = 0; ii < 2; ii++) {
                int i = tid + ii * 512;
                copy_storeA(pa[ii], A, i >> 3, (i & 7) << 3);
                cvt_storeB(pg[ii], Bgh, Bgl, i >> 4, (i & 15) << 2);
                cvt_storeB(pu[ii], Buh, Bul, i >> 4, (i & 15) << 2);
            }
        }
        __syncthreads();
    }

    const int rl = lane >> 2, cp = (lane & 3) * 2;
#pragma unroll
    for (int mf = 0; mf < 2; mf++)
#pragma unroll
        for (int nf = 0; nf < 2; nf++) {
            int row = t0 + wm + mf * 16 + rl;
            int col = f0 + wn + nf * 8 + cp;
            __half* b0 = g_h + ((size_t)e * CAP + row) * FF + col;
            *(__half2*)b0 = __floats2half2_rn(silu_f(ag[mf][nf][0]) * au[mf][nf][0],
                                              silu_f(ag[mf][nf][1]) * au[mf][nf][1]);
            *(__half2*)(b0 + (size_t)8 * FF) =
                            __floats2half2_rn(silu_f(ag[mf][nf][2]) * au[mf][nf][2],
                                              silu_f(ag[mf][nf][3]) * au[mf][nf][3]);
        }
}

// ---- shared down: out = sum_s hs_s @ sd_s^T (initializes out) -------------
// CTA 128M x 128N
__global__ __launch_bounds__(512)
void k_sh_dn(const float* __restrict__ sdw, float* __restrict__ out)
{
    extern __shared__ char sm[];
    const int tid = threadIdx.x, wid = tid >> 5, lane = tid & 31;
    const int t0 = blockIdx.x * 128, d0 = blockIdx.y * 128;
    const int wm = (wid >> 2) * 32, wn = (wid & 3) * 32;
    uint32_t smb = smem_u32(sm);

    const uint32_t aCol = (lane >> 4) * 16;
    const uint32_t offA0 = (uint32_t)(wm + (lane & 15)) * SST_B + aCol;
    const uint32_t offA1 = offA0 + 16 * SST_B;
    const uint32_t offB  = (uint32_t)(wn + ((lane >> 4) << 3) + (lane & 7)) * SST_B
                         + ((lane >> 3) & 1) * 16;

    float ac[2][4][4] = {};
    uint4  pa[2];
    float4 pb[4];

#pragma unroll
    for (int ii = 0; ii < 2; ii++) {
        int i = tid + ii * 512;
        int ra = i >> 3, c8 = (i & 7) << 3;
        pa[ii] = *(const uint4*)(g_hs + ((size_t)t0 + ra) * SFF + c8);
    }
#pragma unroll
    for (int ii = 0; ii < 4; ii++) {
        int i = tid + ii * 512;
        int rb = i >> 4, c4 = (i & 15) << 2;
        pb[ii] = *(const float4*)(sdw + ((size_t)d0 + rb) * SFF + c4);
    }
    {
        char* A = sm; char* Bh = sm + ABYTES; char* Bl = sm + 2 * ABYTES;
#pragma unroll
        for (int ii = 0; ii < 2; ii++) {
            int i = tid + ii * 512;
            copy_storeA(pa[ii], A, i >> 3, (i & 7) << 3);
        }
#pragma unroll
        for (int ii = 0; ii < 4; ii++) {
            int i = tid + ii * 512;
            cvt_storeB(pb[ii], Bh, Bl, i >> 4, (i & 15) << 2);
        }
    }
    __syncthreads();

    for (int it = 0; it < 64; it++) {
        if (it + 1 < 64) {
            int s  = (it + 1) >> 5;
            int kt = ((it + 1) & 31) * 64;
#pragma unroll
            for (int ii = 0; ii < 2; ii++) {
                int i = tid + ii * 512;
                int ra = i >> 3, c8 = (i & 7) << 3;
                pa[ii] = *(const uint4*)(g_hs + ((size_t)s * NT + t0 + ra) * SFF + kt + c8);
            }
#pragma unroll
            for (int ii = 0; ii < 4; ii++) {
                int i = tid + ii * 512;
                int rb = i >> 4, c4 = (i & 15) << 2;
                pb[ii] = *(const float4*)(sdw + ((size_t)s * DM + d0 + rb) * SFF + kt + c4);
            }
        }
        dn_compute(smb + (it & 1) * DN_STG, offA0, offA1, offB, ac);
        if (it + 1 < 64) {
            char* base = sm + ((it + 1) & 1) * DN_STG;
            char* A = base; char* Bh = base + ABYTES; char* Bl = base + 2 * ABYTES;
#pragma unroll
            for (int ii = 0; ii < 2; ii++) {
                int i = tid + ii * 512;
                copy_storeA(pa[ii], A, i >> 3, (i & 7) << 3);
            }
#pragma unroll
            for (int ii = 0; ii < 4; ii++) {
                int i = tid + ii * 512;
                cvt_storeB(pb[ii], Bh, Bl, i >> 4, (i & 15) << 2);
            }
        }
        __syncthreads();
    }

    const int rl = lane >> 2, cp = (lane & 3) * 2;
#pragma unroll
    for (int mf = 0; mf < 2; mf++)
#pragma unroll
        for (int nf = 0; nf < 4; nf++) {
            int row = t0 + wm + mf * 16 + rl;
            int col = d0 + wn + nf * 8 + cp;
            float* b0 = out + (size_t)row * DM + col;
            *(float2*)b0 = make_float2(ac[mf][nf][0], ac[mf][nf][1]);
            *(float2*)(b0 + (size_t)8 * DM) = make_float2(ac[mf][nf][2], ac[mf][nf][3]);
        }
}

// ---- expert down: y = h @ down^T  (plain stores to g_y), CTA 128Mx128N ----
__global__ __launch_bounds__(512)
void k_ex_dn(const float* __restrict__ dw)
{
    const int e = blockIdx.x;
    const int t0 = blockIdx.y * 128, d0 = blockIdx.z * 128;
    if (t0 >= g_counts[e]) return;

    extern __shared__ char sm[];
    const int tid = threadIdx.x, wid = tid >> 5, lane = tid & 31;
    const int wm = (wid >> 2) * 32, wn = (wid & 3) * 32;
    uint32_t smb = smem_u32(sm);

    const uint32_t aCol = (lane >> 4) * 16;
    const uint32_t offA0 = (uint32_t)(wm + (lane & 15)) * SST_B + aCol;
    const uint32_t offA1 = offA0 + 16 * SST_B;
    const uint32_t offB  = (uint32_t)(wn + ((lane >> 4) << 3) + (lane & 7)) * SST_B
                         + ((lane >> 3) & 1) * 16;

    const __half* Asrc = g_h + ((size_t)e * CAP + t0) * FF;
    const float*  Bsrc = dw  + ((size_t)e * DM + d0) * FF;

    float ac[2][4][4] = {};
    uint4  pa[2];
    float4 pb[4];

#pragma unroll
    for (int ii = 0; ii < 2; ii++) {
        int i = tid + ii * 512;
        int ra = i >> 3, c8 = (i & 7) << 3;
        pa[ii] = *(const uint4*)(Asrc + (size_t)ra * FF + c8);
    }
#pragma unroll
    for (int ii = 0; ii < 4; ii++) {
        int i = tid + ii * 512;
        int rb = i >> 4, c4 = (i & 15) << 2;
        pb[ii] = *(const float4*)(Bsrc + (size_t)rb * FF + c4);
    }
    {
        char* A = sm; char* Bh = sm + ABYTES; char* Bl = sm + 2 * ABYTES;
#pragma unroll
        for (int ii = 0; ii < 2; ii++) {
            int i = tid + ii * 512;
            copy_storeA(pa[ii], A, i >> 3, (i & 7) << 3);
        }
#pragma unroll
        for (int ii = 0; ii < 4; ii++) {
            int i = tid + ii * 512;
            cvt_storeB(pb[ii], Bh, Bl, i >> 4, (i & 15) << 2);
        }
    }
    __syncthreads();

    for (int it = 0; it < FF / 64; it++) {
        if (it + 1 < FF / 64) {
            int kt = (it + 1) * 64;
#pragma unroll
            for (int ii = 0; ii < 2; ii++) {
                int i = tid + ii * 512;
                int ra = i >> 3, c8 = (i & 7) << 3;
                pa[ii] = *(const uint4*)(Asrc + (size_t)ra * FF + kt + c8);
            }
#pragma unroll
            for (int ii = 0; ii < 4; ii++) {
                int i = tid + ii * 512;
                int rb = i >> 4, c4 = (i & 15) << 2;
                pb[ii] = *(const float4*)(Bsrc + (size_t)rb * FF + kt + c4);
            }
        }
        dn_compute(smb + (it & 1) * DN_STG, offA0, offA1, offB, ac);
        if (it + 1 < FF / 64) {
            char* base = sm + ((it + 1) & 1) * DN_STG;
            char* A = base; char* Bh = base + ABYTES; char* Bl = base + 2 * ABYTES;
#pragma unroll
            for (int ii = 0; ii < 2; ii++) {
                int i = tid + ii * 512;
                copy_storeA(pa[ii], A, i >> 3, (i & 7) << 3);
            }
#pragma unroll
            for (int ii = 0; ii < 4; ii++) {
                int i = tid + ii * 512;
                cvt_storeB(pb[ii], Bh, Bl, i >> 4, (i & 15) << 2);
            }
        }
        __syncthreads();
    }

    const int rl = lane >> 2, cp = (lane & 3) * 2;
#pragma unroll
    for (int mf = 0; mf < 2; mf++)
#pragma unroll
        for (int nf = 0; nf < 4; nf++) {
            int row = t0 + wm + mf * 16 + rl;
            int col = d0 + wn + nf * 8 + cp;
            float* b0 = g_y + ((size_t)e * CAP + row) * DM + col;
            *(float2*)b0 = make_float2(ac[mf][nf][0], ac[mf][nf][1]);
            *(float2*)(b0 + (size_t)8 * DM) = make_float2(ac[mf][nf][2], ac[mf][nf][3]);
        }
}

// ===========================================================================
// Combine
// ===========================================================================
__global__ __launch_bounds__(256)
void k_combine(float* __restrict__ out)
{
    const int n = blockIdx.x, tid = threadIdx.x;
    int sl[TOPK]; float w[TOPK];
#pragma unroll
    for (int r = 0; r < TOPK; r++) {
        sl[r] = g_pair_slot[n * TOPK + r];
        w[r]  = g_topk_w[n * TOPK + r];
    }
    float* orow = out + (size_t)n * DM;
#pragma unroll
    for (int d = tid * 4; d < DM; d += 1024) {
        float4 acc = *(float4*)(orow + d);
#pragma unroll
        for (int r = 0; r < TOPK; r++) {
            if (sl[r] >= 0) {
                float4 yv = *(const float4*)(g_y + (size_t)sl[r] * DM + d);
                acc.x += w[r] * yv.x; acc.y += w[r] * yv.y;
                acc.z += w[r] * yv.z; acc.w += w[r] * yv.w;
            }
        }
        *(float4*)(orow + d) = acc;
    }
}

// ===========================================================================
// Launch
// ===========================================================================
extern "C" void kernel_launch(void* const* d_in, const int* in_sizes, int n_in,
                              void* d_out, int out_size)
{
    const float* x      = (const float*)d_in[0];
    const float* rw     = (const float*)d_in[1];
    const float* rbias  = (const float*)d_in[2];
    const float* gate_w = (const float*)d_in[3];
    const float* up_w   = (const float*)d_in[4];
    const float* down_w = (const float*)d_in[5];
    const float* sg_w   = (const float*)d_in[6];
    const float* su_w   = (const float*)d_in[7];
    const float* sd_w   = (const float*)d_in[8];
    float* out = (float*)d_out;

    cudaFuncSetAttribute(k_sh_gu, cudaFuncAttributeMaxDynamicSharedMemorySize, GU_SMEM);
    cudaFuncSetAttribute(k_ex_gu, cudaFuncAttributeMaxDynamicSharedMemorySize, GU_SMEM);
    cudaFuncSetAttribute(k_sh_dn, cudaFuncAttributeMaxDynamicSharedMemorySize, DN_SMEM);
    cudaFuncSetAttribute(k_ex_dn, cudaFuncAttributeMaxDynamicSharedMemorySize, DN_SMEM);

    k_cvt_x<<<NT * DM / 1024, 256>>>(x);
    k_router_logits<<<NT / RBM, 256>>>(x, rw);
    k_topk<<<NT, 32>>>(rbias);
    k_dispatch<<<NE, 256>>>();

    k_ex_gu<<<dim3(NE, CAP / 128, FF / 64), 512, GU_SMEM>>>(gate_w, up_w);
    k_sh_gu<<<dim3(NT / 128, SFF / 64, NS), 512, GU_SMEM>>>(sg_w, su_w);

    k_sh_dn<<<dim3(NT / 128, DM / 128), 512, DN_SMEM>>>(sd_w, out);
    k_ex_dn<<<dim3(NE, CAP / 128, DM / 128), 512, DN_SMEM>>>(down_w);

    k_combine<<<NT, 256>>>(out);
}

// round 6
// speedup vs baseline: 4.1649x; 1.1158x over previous
#include <cuda_runtime.h>
#include <cuda_fp16.h>
#include <math.h>
#include <stdint.h>

// ---------------------------------------------------------------------------
// Problem constants
// ---------------------------------------------------------------------------
#define NT   2048
#define DM   2048
#define NE   64
#define TOPK 4
#define FF   512
#define NS   2
#define SFF  2048
#define CAP  256
#define NP   (NT * TOPK)

// ---------------------------------------------------------------------------
// Device scratch
// ---------------------------------------------------------------------------
__device__ float  g_logits[NT * NE];
__device__ int    g_topk_idx[NP];
__device__ float  g_topk_w[NP];
__device__ int    g_pair_slot[NP];
__device__ int    g_tok_table[NE * CAP];
__device__ int    g_counts[NE];
__device__ __half g_xh[NT * DM];
__device__ __half g_h [NE * CAP * FF];
__device__ __half g_hs[NS * NT * SFF];
__device__ float  g_y [(size_t)NE * CAP * DM];

// ---------------------------------------------------------------------------
// Helpers
// ---------------------------------------------------------------------------
__device__ __forceinline__ uint32_t smem_u32(const void* p) {
    uint32_t a;
    asm("{ .reg .u64 t; cvta.to.shared.u64 t, %1; cvt.u32.u64 %0, t; }" : "=r"(a) : "l"(p));
    return a;
}
__device__ __forceinline__ void ldsm4(uint32_t r[4], uint32_t a) {
    asm volatile("ldmatrix.sync.aligned.m8n8.x4.shared.b16 {%0,%1,%2,%3}, [%4];"
        : "=r"(r[0]), "=r"(r[1]), "=r"(r[2]), "=r"(r[3]) : "r"(a));
}
__device__ __forceinline__ void mma_f16(float c[4], const uint32_t a[4], const uint32_t b[2]) {
    asm volatile("mma.sync.aligned.m16n8k16.row.col.f32.f16.f16.f32 "
        "{%0,%1,%2,%3}, {%4,%5,%6,%7}, {%8,%9}, {%0,%1,%2,%3};"
        : "+f"(c[0]), "+f"(c[1]), "+f"(c[2]), "+f"(c[3])
        : "r"(a[0]), "r"(a[1]), "r"(a[2]), "r"(a[3]), "r"(b[0]), "r"(b[1]));
}
__device__ __forceinline__ uint32_t h2u(__half2 h) { return *(uint32_t*)&h; }

#define SST_B 144

__device__ __forceinline__ void cvt_storeB(float4 v, char* hi, char* lo, int r, int c4) {
    __half2 h0 = __floats2half2_rn(v.x, v.y);
    __half2 h1 = __floats2half2_rn(v.z, v.w);
    float2 f0 = __half22float2(h0), f1 = __half22float2(h1);
    __half2 l0 = __floats2half2_rn(v.x - f0.x, v.y - f0.y);
    __half2 l1 = __floats2half2_rn(v.z - f1.x, v.w - f1.y);
    uint32_t off = (uint32_t)(r * SST_B + c4 * 2);
    *(uint2*)(hi + off) = make_uint2(h2u(h0), h2u(h1));
    *(uint2*)(lo + off) = make_uint2(h2u(l0), h2u(l1));
}
__device__ __forceinline__ void copy_storeA(uint4 v, char* dst, int r, int c8) {
    *(uint4*)(dst + (uint32_t)(r * SST_B + c8 * 2)) = v;
}
__device__ __forceinline__ float silu_f(float g) { return g / (1.f + expf(-g)); }

// Stage layouts (3-stage ring)
#define ABYTES 18432                     // 128 rows * 144B
#define BBYTES  9216                     // 64 rows * 144B
#define GU_STG (ABYTES + 4 * BBYTES)     // 55296
#define DN_STG (3 * ABYTES)              // 55296
#define S_STAGES 3
#define GU_SMEM (S_STAGES * GU_STG)      // 165888
#define DN_SMEM (S_STAGES * DN_STG)      // 165888

// Named barriers: FULL(s)=1+s, EMPTY(s)=4+s  (barrier 0 = __syncthreads)
#define BAR_SYNC(id)   asm volatile("bar.sync %0, 512;"   :: "r"(id) : "memory")
#define BAR_ARRIVE(id) asm volatile("bar.arrive %0, 512;" :: "r"(id) : "memory")

// ===========================================================================
// 0) x -> fp16
// ===========================================================================
__global__ __launch_bounds__(256)
void k_cvt_x(const float* __restrict__ x)
{
    int i = (blockIdx.x * 256 + threadIdx.x) * 4;
    float4 v = *(const float4*)(x + i);
    __half2 h0 = __floats2half2_rn(v.x, v.y);
    __half2 h1 = __floats2half2_rn(v.z, v.w);
    *(uint2*)(g_xh + i) = make_uint2(h2u(h0), h2u(h1));
}

// ===========================================================================
// 1) Router logits (SIMT fp32)
// ===========================================================================
#define RBM 64
#define RBK 16
__global__ __launch_bounds__(256)
void k_router_logits(const float* __restrict__ x, const float* __restrict__ rw)
{
    __shared__ __align__(16) float As[RBK][RBM];
    __shared__ __align__(16) float Bs[RBK][RBM];
    const int tid = threadIdx.x;
    const int t0  = blockIdx.x * RBM;
    const int lr  = tid >> 2, lk = (tid & 3) * 4;
    const int ty4 = (tid >> 4) * 4, tx4 = (tid & 15) * 4;
    float acc[4][4];
#pragma unroll
    for (int i = 0; i < 4; i++)
#pragma unroll
        for (int j = 0; j < 4; j++) acc[i][j] = 0.f;
    for (int kt = 0; kt < DM; kt += RBK) {
        float4 a = *(const float4*)(x + (size_t)(t0 + lr) * DM + kt + lk);
        As[lk+0][lr] = a.x; As[lk+1][lr] = a.y; As[lk+2][lr] = a.z; As[lk+3][lr] = a.w;
        float4 b = *(const float4*)(rw + (size_t)lr * DM + kt + lk);
        Bs[lk+0][lr] = b.x; Bs[lk+1][lr] = b.y; Bs[lk+2][lr] = b.z; Bs[lk+3][lr] = b.w;
        __syncthreads();
#pragma unroll
        for (int k = 0; k < RBK; k++) {
            float4 av = *(const float4*)&As[k][ty4];
            float4 bv = *(const float4*)&Bs[k][tx4];
            float a4[4] = {av.x, av.y, av.z, av.w};
            float b4[4] = {bv.x, bv.y, bv.z, bv.w};
#pragma unroll
            for (int i = 0; i < 4; i++)
#pragma unroll
                for (int j = 0; j < 4; j++) acc[i][j] += a4[i] * b4[j];
        }
        __syncthreads();
    }
#pragma unroll
    for (int i = 0; i < 4; i++)
#pragma unroll
        for (int j = 0; j < 4; j++)
            g_logits[(size_t)(t0 + ty4 + i) * NE + tx4 + j] = acc[i][j];
}

// ===========================================================================
// 2) Top-k (1 warp / token)
// ===========================================================================
__global__ void k_topk(const float* __restrict__ bias)
{
    const int n = blockIdx.x, lane = threadIdx.x;
    float l0 = g_logits[n * NE + lane];
    float l1 = g_logits[n * NE + 32 + lane];
    float s0 = l0 + bias[lane];
    float s1 = l1 + bias[32 + lane];
    int ch_idx[TOPK]; float ch_l[TOPK];
#pragma unroll
    for (int r = 0; r < TOPK; r++) {
        float v = s0; int idx = lane;
        if (s1 > v) { v = s1; idx = lane + 32; }
#pragma unroll
        for (int off = 16; off > 0; off >>= 1) {
            float ov = __shfl_xor_sync(0xffffffffu, v, off);
            int   oi = __shfl_xor_sync(0xffffffffu, idx, off);
            if (ov > v || (ov == v && oi < idx)) { v = ov; idx = oi; }
        }
        int owner = (idx < 32) ? idx : (idx - 32);
        float rawA = __shfl_sync(0xffffffffu, l0, owner);
        float rawB = __shfl_sync(0xffffffffu, l1, owner);
        ch_idx[r] = idx;
        ch_l[r]   = (idx < 32) ? rawA : rawB;
        if (lane == owner) { if (idx < 32) s0 = -INFINITY; else s1 = -INFINITY; }
    }
    if (lane == 0) {
        float m = ch_l[0];
#pragma unroll
        for (int r = 1; r < TOPK; r++) m = fmaxf(m, ch_l[r]);
        float w[TOPK], sum = 0.f;
#pragma unroll
        for (int r = 0; r < TOPK; r++) { w[r] = expf(ch_l[r] - m); sum += w[r]; }
        float inv = 1.f / sum;
#pragma unroll
        for (int r = 0; r < TOPK; r++) {
            g_topk_idx[n * TOPK + r] = ch_idx[r];
            g_topk_w[n * TOPK + r]   = w[r] * inv;
        }
    }
}

// ===========================================================================
// 3) Dispatch: zero counts -> atomic slot assignment -> tail fill.
//    Slot ordering is arbitrary; with no capacity overflow (mean load 128,
//    CAP 256) the result is an order-invariant permutation: identical output.
// ===========================================================================
__global__ void k_zero_counts() { if (threadIdx.x < NE) g_counts[threadIdx.x] = 0; }

__global__ __launch_bounds__(256)
void k_dispatch_atomic()
{
    int p = blockIdx.x * 256 + threadIdx.x;
    int e = g_topk_idx[p];
    int slot = atomicAdd(&g_counts[e], 1);
    if (slot < CAP) {
        g_tok_table[e * CAP + slot] = p >> 2;
        g_pair_slot[p] = e * CAP + slot;
    } else {
        g_pair_slot[p] = -1;
    }
}

__global__ void k_tail_fill()
{
    int e = blockIdx.x;
    int cnt = g_counts[e]; if (cnt > CAP) cnt = CAP;
    for (int i = cnt + threadIdx.x; i < CAP; i += 256)
        g_tok_table[e * CAP + i] = 0;
    if (threadIdx.x == 0) g_counts[e] = cnt;
}

// ===========================================================================
// Consumer compute cores
// ===========================================================================
// GU: 8 consumer warps on 128Mx64N; warp tile 32Mx32N
__device__ __forceinline__ void gu_cons(uint32_t ub,
    uint32_t offA0, uint32_t offA1, uint32_t offB,
    float ag[2][4][4], float au[2][4][4])
{
    const uint32_t uA = ub, uBgh = ub + ABYTES, uBgl = uBgh + BBYTES;
    const uint32_t uBuh = uBgl + BBYTES, uBul = uBuh + BBYTES;
#pragma unroll
    for (int ks = 0; ks < 4; ks++) {
        uint32_t kb = ks * 32;
        uint32_t ah[2][4], bgh[8], bgl[8], buh[8], bul[8];
        ldsm4(ah[0], uA + offA0 + kb); ldsm4(ah[1], uA + offA1 + kb);
        ldsm4(bgh,     uBgh + offB + kb); ldsm4(bgh + 4, uBgh + offB + 16 * SST_B + kb);
        ldsm4(bgl,     uBgl + offB + kb); ldsm4(bgl + 4, uBgl + offB + 16 * SST_B + kb);
        ldsm4(buh,     uBuh + offB + kb); ldsm4(buh + 4, uBuh + offB + 16 * SST_B + kb);
        ldsm4(bul,     uBul + offB + kb); ldsm4(bul + 4, uBul + offB + 16 * SST_B + kb);
#pragma unroll
        for (int mf = 0; mf < 2; mf++)
#pragma unroll
            for (int nf = 0; nf < 4; nf++) {
                mma_f16(ag[mf][nf], ah[mf], &bgh[nf * 2]);
                mma_f16(ag[mf][nf], ah[mf], &bgl[nf * 2]);
                mma_f16(au[mf][nf], ah[mf], &buh[nf * 2]);
                mma_f16(au[mf][nf], ah[mf], &bul[nf * 2]);
            }
    }
}

// DN: 8 consumer warps on 128Mx128N; warp tile 32Mx64N
__device__ __forceinline__ void dn_cons(uint32_t ub,
    uint32_t offA0, uint32_t offA1, uint32_t offB,
    float ac[2][8][4])
{
    const uint32_t uA = ub, uBh = ub + ABYTES, uBl = ub + 2 * ABYTES;
#pragma unroll
    for (int ks = 0; ks < 4; ks++) {
        uint32_t kb = ks * 32;
        uint32_t ah[2][4], bh[16], bl[16];
        ldsm4(ah[0], uA + offA0 + kb); ldsm4(ah[1], uA + offA1 + kb);
#pragma unroll
        for (int q = 0; q < 4; q++) {
            ldsm4(bh + 4 * q, uBh + offB + q * 16 * SST_B + kb);
            ldsm4(bl + 4 * q, uBl + offB + q * 16 * SST_B + kb);
        }
#pragma unroll
        for (int mf = 0; mf < 2; mf++)
#pragma unroll
            for (int nf = 0; nf < 8; nf++) {
                mma_f16(ac[mf][nf], ah[mf], &bh[nf * 2]);
                mma_f16(ac[mf][nf], ah[mf], &bl[nf * 2]);
            }
    }
}

// ===========================================================================
// GU kernels (warp-specialized): warps 0-7 consumers, 8-15 producers
// ===========================================================================
__global__ __launch_bounds__(512)
void k_sh_gu(const float* __restrict__ sgw, const float* __restrict__ suw)
{
    extern __shared__ char sm[];
    const int tid = threadIdx.x, wid = tid >> 5, lane = tid & 31;
    const int t0 = blockIdx.x * 128, f0 = blockIdx.y * 64, s = blockIdx.z;
    uint32_t smb = smem_u32(sm);
    const int NIT = DM / 64;

    if (wid < 8) {
        const int wm = (wid >> 1) * 32, wn = (wid & 1) * 32;
        const uint32_t offA0 = (uint32_t)(wm + (lane & 15)) * SST_B + (lane >> 4) * 16;
        const uint32_t offA1 = offA0 + 16 * SST_B;
        const uint32_t offB  = (uint32_t)(wn + ((lane >> 4) << 3) + (lane & 7)) * SST_B
                             + ((lane >> 3) & 1) * 16;
        float ag[2][4][4] = {}, au[2][4][4] = {};
        for (int it = 0; it < NIT; it++) {
            int st = it % S_STAGES;
            BAR_SYNC(1 + st);
            gu_cons(smb + st * GU_STG, offA0, offA1, offB, ag, au);
            BAR_ARRIVE(4 + st);
        }
        const int rl = lane >> 2, cp = (lane & 3) * 2;
#pragma unroll
        for (int mf = 0; mf < 2; mf++)
#pragma unroll
            for (int nf = 0; nf < 4; nf++) {
                int row = t0 + wm + mf * 16 + rl;
                int col = f0 + wn + nf * 8 + cp;
                __half* b0 = g_hs + ((size_t)s * NT + row) * SFF + col;
                *(__half2*)b0 = __floats2half2_rn(silu_f(ag[mf][nf][0]) * au[mf][nf][0],
                                                  silu_f(ag[mf][nf][1]) * au[mf][nf][1]);
                *(__half2*)(b0 + (size_t)8 * SFF) =
                                __floats2half2_rn(silu_f(ag[mf][nf][2]) * au[mf][nf][2],
                                                  silu_f(ag[mf][nf][3]) * au[mf][nf][3]);
            }
    } else {
        const int ptid = tid - 256;
        const __half* Asrc = g_xh + (size_t)t0 * DM;
        const float*  Gsrc = sgw + ((size_t)s * SFF + f0) * DM;
        const float*  Usrc = suw + ((size_t)s * SFF + f0) * DM;
        uint4 va[4]; float4 vg[4], vu[4];
#pragma unroll
        for (int j = 0; j < 4; j++) {
            int ia = ptid + j * 256;
            va[j] = *(const uint4*)(Asrc + (size_t)(ia >> 3) * DM + ((ia & 7) << 3));
            vg[j] = *(const float4*)(Gsrc + (size_t)(ia >> 4) * DM + ((ia & 15) << 2));
            vu[j] = *(const float4*)(Usrc + (size_t)(ia >> 4) * DM + ((ia & 15) << 2));
        }
        for (int it = 0; it < NIT; it++) {
            int st = it % S_STAGES;
            if (it >= S_STAGES) BAR_SYNC(4 + st);
            char* base = sm + st * GU_STG;
            char* A = base; char* Bgh = base + ABYTES; char* Bgl = Bgh + BBYTES;
            char* Buh = Bgl + BBYTES; char* Bul = Buh + BBYTES;
#pragma unroll
            for (int j = 0; j < 4; j++) {
                int ia = ptid + j * 256;
                copy_storeA(va[j], A, ia >> 3, (ia & 7) << 3);
                cvt_storeB(vg[j], Bgh, Bgl, ia >> 4, (ia & 15) << 2);
                cvt_storeB(vu[j], Buh, Bul, ia >> 4, (ia & 15) << 2);
            }
            BAR_ARRIVE(1 + st);
            if (it + 1 < NIT) {
                int kt = (it + 1) * 64;
#pragma unroll
                for (int j = 0; j < 4; j++) {
                    int ia = ptid + j * 256;
                    va[j] = *(const uint4*)(Asrc + (size_t)(ia >> 3) * DM + kt + ((ia & 7) << 3));
                    vg[j] = *(const float4*)(Gsrc + (size_t)(ia >> 4) * DM + kt + ((ia & 15) << 2));
                    vu[j] = *(const float4*)(Usrc + (size_t)(ia >> 4) * DM + kt + ((ia & 15) << 2));
                }
            }
        }
    }
}

__global__ __launch_bounds__(512)
void k_ex_gu(const float* __restrict__ gw, const float* __restrict__ uw)
{
    const int e = blockIdx.x;
    const int t0 = blockIdx.y * 128, f0 = blockIdx.z * 64;
    if (t0 >= g_counts[e]) return;

    extern __shared__ char sm[];
    __shared__ int toks[128];
    const int tid = threadIdx.x, wid = tid >> 5, lane = tid & 31;
    uint32_t smb = smem_u32(sm);
    const int NIT = DM / 64;

    if (tid < 128) toks[tid] = g_tok_table[e * CAP + t0 + tid];
    __syncthreads();

    if (wid < 8) {
        const int wm = (wid >> 1) * 32, wn = (wid & 1) * 32;
        const uint32_t offA0 = (uint32_t)(wm + (lane & 15)) * SST_B + (lane >> 4) * 16;
        const uint32_t offA1 = offA0 + 16 * SST_B;
        const uint32_t offB  = (uint32_t)(wn + ((lane >> 4) << 3) + (lane & 7)) * SST_B
                             + ((lane >> 3) & 1) * 16;
        float ag[2][4][4] = {}, au[2][4][4] = {};
        for (int it = 0; it < NIT; it++) {
            int st = it % S_STAGES;
            BAR_SYNC(1 + st);
            gu_cons(smb + st * GU_STG, offA0, offA1, offB, ag, au);
            BAR_ARRIVE(4 + st);
        }
        const int rl = lane >> 2, cp = (lane & 3) * 2;
#pragma unroll
        for (int mf = 0; mf < 2; mf++)
#pragma unroll
            for (int nf = 0; nf < 4; nf++) {
                int row = t0 + wm + mf * 16 + rl;
                int col = f0 + wn + nf * 8 + cp;
                __half* b0 = g_h + ((size_t)e * CAP + row) * FF + col;
                *(__half2*)b0 = __floats2half2_rn(silu_f(ag[mf][nf][0]) * au[mf][nf][0],
                                                  silu_f(ag[mf][nf][1]) * au[mf][nf][1]);
                *(__half2*)(b0 + (size_t)8 * FF) =
                                __floats2half2_rn(silu_f(ag[mf][nf][2]) * au[mf][nf][2],
                                                  silu_f(ag[mf][nf][3]) * au[mf][nf][3]);
            }
    } else {
        const int ptid = tid - 256;
        const float* Gsrc = gw + ((size_t)e * FF + f0) * DM;
        const float* Usrc = uw + ((size_t)e * FF + f0) * DM;
        uint4 va[4]; float4 vg[4], vu[4];
#pragma unroll
        for (int j = 0; j < 4; j++) {
            int ia = ptid + j * 256;
            va[j] = *(const uint4*)(g_xh + (size_t)toks[ia >> 3] * DM + ((ia & 7) << 3));
            vg[j] = *(const float4*)(Gsrc + (size_t)(ia >> 4) * DM + ((ia & 15) << 2));
            vu[j] = *(const float4*)(Usrc + (size_t)(ia >> 4) * DM + ((ia & 15) << 2));
        }
        for (int it = 0; it < NIT; it++) {
            int st = it % S_STAGES;
            if (it >= S_STAGES) BAR_SYNC(4 + st);
            char* base = sm + st * GU_STG;
            char* A = base; char* Bgh = base + ABYTES; char* Bgl = Bgh + BBYTES;
            char* Buh = Bgl + BBYTES; char* Bul = Buh + BBYTES;
#pragma unroll
            for (int j = 0; j < 4; j++) {
                int ia = ptid + j * 256;
                copy_storeA(va[j], A, ia >> 3, (ia & 7) << 3);
                cvt_storeB(vg[j], Bgh, Bgl, ia >> 4, (ia & 15) << 2);
                cvt_storeB(vu[j], Buh, Bul, ia >> 4, (ia & 15) << 2);
            }
            BAR_ARRIVE(1 + st);
            if (it + 1 < NIT) {
                int kt = (it + 1) * 64;
#pragma unroll
                for (int j = 0; j < 4; j++) {
                    int ia = ptid + j * 256;
                    va[j] = *(const uint4*)(g_xh + (size_t)toks[ia >> 3] * DM + kt + ((ia & 7) << 3));
                    vg[j] = *(const float4*)(Gsrc + (size_t)(ia >> 4) * DM + kt + ((ia & 15) << 2));
                    vu[j] = *(const float4*)(Usrc + (size_t)(ia >> 4) * DM + kt + ((ia & 15) << 2));
                }
            }
        }
    }
}

// ===========================================================================
// DN kernels (warp-specialized), CTA 128Mx128N
// ===========================================================================
__global__ __launch_bounds__(512)
void k_sh_dn(const float* __restrict__ sdw, float* __restrict__ out)
{
    extern __shared__ char sm[];
    const int tid = threadIdx.x, wid = tid >> 5, lane = tid & 31;
    const int t0 = blockIdx.x * 128, d0 = blockIdx.y * 128;
    uint32_t smb = smem_u32(sm);
    const int NIT = 64;   // 2 shared experts x 32 K-tiles

    if (wid < 8) {
        const int wm = (wid >> 1) * 32, wn = (wid & 1) * 64;
        const uint32_t offA0 = (uint32_t)(wm + (lane & 15)) * SST_B + (lane >> 4) * 16;
        const uint32_t offA1 = offA0 + 16 * SST_B;
        const uint32_t offB  = (uint32_t)(wn + ((lane >> 4) << 3) + (lane & 7)) * SST_B
                             + ((lane >> 3) & 1) * 16;
        float ac[2][8][4] = {};
        for (int it = 0; it < NIT; it++) {
            int st = it % S_STAGES;
            BAR_SYNC(1 + st);
            dn_cons(smb + st * DN_STG, offA0, offA1, offB, ac);
            BAR_ARRIVE(4 + st);
        }
        const int rl = lane >> 2, cp = (lane & 3) * 2;
#pragma unroll
        for (int mf = 0; mf < 2; mf++)
#pragma unroll
            for (int nf = 0; nf < 8; nf++) {
                int row = t0 + wm + mf * 16 + rl;
                int col = d0 + wn + nf * 8 + cp;
                float* b0 = out + (size_t)row * DM + col;
                *(float2*)b0 = make_float2(ac[mf][nf][0], ac[mf][nf][1]);
                *(float2*)(b0 + (size_t)8 * DM) = make_float2(ac[mf][nf][2], ac[mf][nf][3]);
            }
    } else {
        const int ptid = tid - 256;
        uint4 va[4]; float4 vb[8];
#pragma unroll
        for (int j = 0; j < 4; j++) {
            int ia = ptid + j * 256;
            va[j] = *(const uint4*)(g_hs + ((size_t)t0 + (ia >> 3)) * SFF + ((ia & 7) << 3));
        }
#pragma unroll
        for (int j = 0; j < 8; j++) {
            int ib = ptid + j * 256;
            vb[j] = *(const float4*)(sdw + ((size_t)d0 + (ib >> 4)) * SFF + ((ib & 15) << 2));
        }
        for (int it = 0; it < NIT; it++) {
            int st = it % S_STAGES;
            if (it >= S_STAGES) BAR_SYNC(4 + st);
            char* base = sm + st * DN_STG;
            char* A = base; char* Bh = base + ABYTES; char* Bl = base + 2 * ABYTES;
#pragma unroll
            for (int j = 0; j < 4; j++) {
                int ia = ptid + j * 256;
                copy_storeA(va[j], A, ia >> 3, (ia & 7) << 3);
            }
#pragma unroll
            for (int j = 0; j < 8; j++) {
                int ib = ptid + j * 256;
                cvt_storeB(vb[j], Bh, Bl, ib >> 4, (ib & 15) << 2);
            }
            BAR_ARRIVE(1 + st);
            if (it + 1 < NIT) {
                int s2 = (it + 1) >> 5;
                int kt = ((it + 1) & 31) * 64;
#pragma unroll
                for (int j = 0; j < 4; j++) {
                    int ia = ptid + j * 256;
                    va[j] = *(const uint4*)(g_hs + ((size_t)s2 * NT + t0 + (ia >> 3)) * SFF + kt + ((ia & 7) << 3));
                }
#pragma unroll
                for (int j = 0; j < 8; j++) {
                    int ib = ptid + j * 256;
                    vb[j] = *(const float4*)(sdw + ((size_t)s2 * DM + d0 + (ib >> 4)) * SFF + kt + ((ib & 15) << 2));
                }
            }
        }
    }
}

__global__ __launch_bounds__(512)
void k_ex_dn(const float* __restrict__ dw)
{
    const int e = blockIdx.x;
    const int t0 = blockIdx.y * 128, d0 = blockIdx.z * 128;
    if (t0 >= g_counts[e]) return;

    extern __shared__ char sm[];
    const int tid = threadIdx.x, wid = tid >> 5, lane = tid & 31;
    uint32_t smb = smem_u32(sm);
    const int NIT = FF / 64;  // 8

    if (wid < 8) {
        const int wm = (wid >> 1) * 32, wn = (wid & 1) * 64;
        const uint32_t offA0 = (uint32_t)(wm + (lane & 15)) * SST_B + (lane >> 4) * 16;
        const uint32_t offA1 = offA0 + 16 * SST_B;
        const uint32_t offB  = (uint32_t)(wn + ((lane >> 4) << 3) + (lane & 7)) * SST_B
                             + ((lane >> 3) & 1) * 16;
        float ac[2][8][4] = {};
        for (int it = 0; it < NIT; it++) {
            int st = it % S_STAGES;
            BAR_SYNC(1 + st);
            dn_cons(smb + st * DN_STG, offA0, offA1, offB, ac);
            BAR_ARRIVE(4 + st);
        }
        const int rl = lane >> 2, cp = (lane & 3) * 2;
#pragma unroll
        for (int mf = 0; mf < 2; mf++)
#pragma unroll
            for (int nf = 0; nf < 8; nf++) {
                int row = t0 + wm + mf * 16 + rl;
                int col = d0 + wn + nf * 8 + cp;
                float* b0 = g_y + ((size_t)e * CAP + row) * DM + col;
                *(float2*)b0 = make_float2(ac[mf][nf][0], ac[mf][nf][1]);
                *(float2*)(b0 + (size_t)8 * DM) = make_float2(ac[mf][nf][2], ac[mf][nf][3]);
            }
    } else {
        const int ptid = tid - 256;
        const __half* Asrc = g_h + ((size_t)e * CAP + t0) * FF;
        const float*  Bsrc = dw  + ((size_t)e * DM + d0) * FF;
        uint4 va[4]; float4 vb[8];
#pragma unroll
        for (int j = 0; j < 4; j++) {
            int ia = ptid + j * 256;
            va[j] = *(const uint4*)(Asrc + (size_t)(ia >> 3) * FF + ((ia & 7) << 3));
        }
#pragma unroll
        for (int j = 0; j < 8; j++) {
            int ib = ptid + j * 256;
            vb[j] = *(const float4*)(Bsrc + (size_t)(ib >> 4) * FF + ((ib & 15) << 2));
        }
        for (int it = 0; it < NIT; it++) {
            int st = it % S_STAGES;
            if (it >= S_STAGES) BAR_SYNC(4 + st);
            char* base = sm + st * DN_STG;
            char* A = base; char* Bh = base + ABYTES; char* Bl = base + 2 * ABYTES;
#pragma unroll
            for (int j = 0; j < 4; j++) {
                int ia = ptid + j * 256;
                copy_storeA(va[j], A, ia >> 3, (ia & 7) << 3);
            }
#pragma unroll
            for (int j = 0; j < 8; j++) {
                int ib = ptid + j * 256;
                cvt_storeB(vb[j], Bh, Bl, ib >> 4, (ib & 15) << 2);
            }
            BAR_ARRIVE(1 + st);
            if (it + 1 < NIT) {
                int kt = (it + 1) * 64;
#pragma unroll
                for (int j = 0; j < 4; j++) {
                    int ia = ptid + j * 256;
                    va[j] = *(const uint4*)(Asrc + (size_t)(ia >> 3) * FF + kt + ((ia & 7) << 3));
                }
#pragma unroll
                for (int j = 0; j < 8; j++) {
                    int ib = ptid + j * 256;
                    vb[j] = *(const float4*)(Bsrc + (size_t)(ib >> 4) * FF + kt + ((ib & 15) << 2));
                }
            }
        }
    }
}

// ===========================================================================
// Combine
// ===========================================================================
__global__ __launch_bounds__(256)
void k_combine(float* __restrict__ out)
{
    const int n = blockIdx.x, tid = threadIdx.x;
    int sl[TOPK]; float w[TOPK];
#pragma unroll
    for (int r = 0; r < TOPK; r++) {
        sl[r] = g_pair_slot[n * TOPK + r];
        w[r]  = g_topk_w[n * TOPK + r];
    }
    float* orow = out + (size_t)n * DM;
#pragma unroll
    for (int d = tid * 4; d < DM; d += 1024) {
        float4 acc = *(float4*)(orow + d);
#pragma unroll
        for (int r = 0; r < TOPK; r++) {
            if (sl[r] >= 0) {
                float4 yv = *(const float4*)(g_y + (size_t)sl[r] * DM + d);
                acc.x += w[r] * yv.x; acc.y += w[r] * yv.y;
                acc.z += w[r] * yv.z; acc.w += w[r] * yv.w;
            }
        }
        *(float4*)(orow + d) = acc;
    }
}

// ===========================================================================
// Launch
// ===========================================================================
extern "C" void kernel_launch(void* const* d_in, const int* in_sizes, int n_in,
                              void* d_out, int out_size)
{
    const float* x      = (const float*)d_in[0];
    const float* rw     = (const float*)d_in[1];
    const float* rbias  = (const float*)d_in[2];
    const float* gate_w = (const float*)d_in[3];
    const float* up_w   = (const float*)d_in[4];
    const float* down_w = (const float*)d_in[5];
    const float* sg_w   = (const float*)d_in[6];
    const float* su_w   = (const float*)d_in[7];
    const float* sd_w   = (const float*)d_in[8];
    float* out = (float*)d_out;

    cudaFuncSetAttribute(k_sh_gu, cudaFuncAttributeMaxDynamicSharedMemorySize, GU_SMEM);
    cudaFuncSetAttribute(k_ex_gu, cudaFuncAttributeMaxDynamicSharedMemorySize, GU_SMEM);
    cudaFuncSetAttribute(k_sh_dn, cudaFuncAttributeMaxDynamicSharedMemorySize, DN_SMEM);
    cudaFuncSetAttribute(k_ex_dn, cudaFuncAttributeMaxDynamicSharedMemorySize, DN_SMEM);

    k_cvt_x<<<NT * DM / 1024, 256>>>(x);
    k_router_logits<<<NT / RBM, 256>>>(x, rw);
    k_topk<<<NT, 32>>>(rbias);
    k_zero_counts<<<1, 64>>>();
    k_dispatch_atomic<<<NP / 256, 256>>>();
    k_tail_fill<<<NE, 256>>>();

    k_ex_gu<<<dim3(NE, CAP / 128, FF / 64), 512, GU_SMEM>>>(gate_w, up_w);
    k_sh_gu<<<dim3(NT / 128, SFF / 64, NS), 512, GU_SMEM>>>(sg_w, su_w);

    k_sh_dn<<<dim3(NT / 128, DM / 128), 512, DN_SMEM>>>(sd_w, out);
    k_ex_dn<<<dim3(NE, CAP / 128, DM / 128), 512, DN_SMEM>>>(down_w);

    k_combine<<<NT, 256>>>(out);
}

// round 8
// speedup vs baseline: 5.7185x; 1.3730x over previous
#include <cuda_runtime.h>
#include <cuda_fp16.h>
#include <math.h>
#include <stdint.h>

// ---------------------------------------------------------------------------
// Problem constants
// ---------------------------------------------------------------------------
#define NT   2048
#define DM   2048
#define NE   64
#define TOPK 4
#define FF   512
#define NS   2
#define SFF  2048
#define CAP  256
#define NP   (NT * TOPK)

// ---------------------------------------------------------------------------
// Device scratch
// ---------------------------------------------------------------------------
__device__ float  g_logits[NT * NE];
__device__ int    g_topk_idx[NP];
__device__ float  g_topk_w[NP];
__device__ int    g_pair_slot[NP];
__device__ int    g_tok_table[NE * CAP];
__device__ int    g_counts[NE];
__device__ __half g_xh[NT * DM];
__device__ __half g_h [NE * CAP * FF];
__device__ __half g_hs[NS * NT * SFF];
__device__ float  g_y [(size_t)NE * CAP * DM];

// ---------------------------------------------------------------------------
// Helpers
// ---------------------------------------------------------------------------
__device__ __forceinline__ uint32_t smem_u32(const void* p) {
    uint32_t a;
    asm("{ .reg .u64 t; cvta.to.shared.u64 t, %1; cvt.u32.u64 %0, t; }" : "=r"(a) : "l"(p));
    return a;
}
__device__ __forceinline__ void ldsm4(uint32_t r[4], uint32_t a) {
    asm volatile("ldmatrix.sync.aligned.m8n8.x4.shared.b16 {%0,%1,%2,%3}, [%4];"
        : "=r"(r[0]), "=r"(r[1]), "=r"(r[2]), "=r"(r[3]) : "r"(a));
}
__device__ __forceinline__ void mma_f16(float c[4], const uint32_t a[4], const uint32_t b[2]) {
    asm volatile("mma.sync.aligned.m16n8k16.row.col.f32.f16.f16.f32 "
        "{%0,%1,%2,%3}, {%4,%5,%6,%7}, {%8,%9}, {%0,%1,%2,%3};"
        : "+f"(c[0]), "+f"(c[1]), "+f"(c[2]), "+f"(c[3])
        : "r"(a[0]), "r"(a[1]), "r"(a[2]), "r"(a[3]), "r"(b[0]), "r"(b[1]));
}
__device__ __forceinline__ uint32_t h2u(__half2 h) { return *(uint32_t*)&h; }

#define SST_B 144

// B: fp32 -> fp16 single (round-to-nearest)
__device__ __forceinline__ void cvt_storeBh(float4 v, char* hi, int r, int c4) {
    __half2 h0 = __floats2half2_rn(v.x, v.y);
    __half2 h1 = __floats2half2_rn(v.z, v.w);
    *(uint2*)(hi + (uint32_t)(r * SST_B + c4 * 2)) = make_uint2(h2u(h0), h2u(h1));
}
__device__ __forceinline__ void copy_storeA(uint4 v, char* dst, int r, int c8) {
    *(uint4*)(dst + (uint32_t)(r * SST_B + c8 * 2)) = v;
}
__device__ __forceinline__ float silu_f(float g) { return g / (1.f + expf(-g)); }

// Stage layouts (3-stage ring)
#define ABYTES 18432                     // 128 rows * 144B
#define BBYTES  9216                     // 64 rows * 144B
#define GU_STG (ABYTES + 2 * BBYTES)     // A | Bg | Bu = 36864
#define DN_STG (2 * ABYTES)              // A | B(128 rows) = 36864
#define S_STAGES 3
#define GU_SMEM (S_STAGES * GU_STG)      // 110592
#define DN_SMEM (S_STAGES * DN_STG)      // 110592

// Named barriers: FULL(s)=1+s, EMPTY(s)=4+s
#define BAR_SYNC(id)   asm volatile("bar.sync %0, 512;"   :: "r"(id) : "memory")
#define BAR_ARRIVE(id) asm volatile("bar.arrive %0, 512;" :: "r"(id) : "memory")

// ===========================================================================
// 0) x -> fp16 (+ zero expert counts)
// ===========================================================================
__global__ __launch_bounds__(256)
void k_cvt_x(const float* __restrict__ x)
{
    if (blockIdx.x == 0 && threadIdx.x < NE) g_counts[threadIdx.x] = 0;
    int i = (blockIdx.x * 256 + threadIdx.x) * 4;
    float4 v = *(const float4*)(x + i);
    __half2 h0 = __floats2half2_rn(v.x, v.y);
    __half2 h1 = __floats2half2_rn(v.z, v.w);
    *(uint2*)(g_xh + i) = make_uint2(h2u(h0), h2u(h1));
}

// ===========================================================================
// 1) Router logits (SIMT fp32)
// ===========================================================================
#define RBM 64
#define RBK 16
__global__ __launch_bounds__(256)
void k_router_logits(const float* __restrict__ x, const float* __restrict__ rw)
{
    __shared__ __align__(16) float As[RBK][RBM];
    __shared__ __align__(16) float Bs[RBK][RBM];
    const int tid = threadIdx.x;
    const int t0  = blockIdx.x * RBM;
    const int lr  = tid >> 2, lk = (tid & 3) * 4;
    const int ty4 = (tid >> 4) * 4, tx4 = (tid & 15) * 4;
    float acc[4][4];
#pragma unroll
    for (int i = 0; i < 4; i++)
#pragma unroll
        for (int j = 0; j < 4; j++) acc[i][j] = 0.f;
    for (int kt = 0; kt < DM; kt += RBK) {
        float4 a = *(const float4*)(x + (size_t)(t0 + lr) * DM + kt + lk);
        As[lk+0][lr] = a.x; As[lk+1][lr] = a.y; As[lk+2][lr] = a.z; As[lk+3][lr] = a.w;
        float4 b = *(const float4*)(rw + (size_t)lr * DM + kt + lk);
        Bs[lk+0][lr] = b.x; Bs[lk+1][lr] = b.y; Bs[lk+2][lr] = b.z; Bs[lk+3][lr] = b.w;
        __syncthreads();
#pragma unroll
        for (int k = 0; k < RBK; k++) {
            float4 av = *(const float4*)&As[k][ty4];
            float4 bv = *(const float4*)&Bs[k][tx4];
            float a4[4] = {av.x, av.y, av.z, av.w};
            float b4[4] = {bv.x, bv.y, bv.z, bv.w};
#pragma unroll
            for (int i = 0; i < 4; i++)
#pragma unroll
                for (int j = 0; j < 4; j++) acc[i][j] += a4[i] * b4[j];
        }
        __syncthreads();
    }
#pragma unroll
    for (int i = 0; i < 4; i++)
#pragma unroll
        for (int j = 0; j < 4; j++)
            g_logits[(size_t)(t0 + ty4 + i) * NE + tx4 + j] = acc[i][j];
}

// ===========================================================================
// 2) Top-k (1 warp / token)
// ===========================================================================
__global__ void k_topk(const float* __restrict__ bias)
{
    const int n = blockIdx.x, lane = threadIdx.x;
    float l0 = g_logits[n * NE + lane];
    float l1 = g_logits[n * NE + 32 + lane];
    float s0 = l0 + bias[lane];
    float s1 = l1 + bias[32 + lane];
    int ch_idx[TOPK]; float ch_l[TOPK];
#pragma unroll
    for (int r = 0; r < TOPK; r++) {
        float v = s0; int idx = lane;
        if (s1 > v) { v = s1; idx = lane + 32; }
#pragma unroll
        for (int off = 16; off > 0; off >>= 1) {
            float ov = __shfl_xor_sync(0xffffffffu, v, off);
            int   oi = __shfl_xor_sync(0xffffffffu, idx, off);
            if (ov > v || (ov == v && oi < idx)) { v = ov; idx = oi; }
        }
        int owner = (idx < 32) ? idx : (idx - 32);
        float rawA = __shfl_sync(0xffffffffu, l0, owner);
        float rawB = __shfl_sync(0xffffffffu, l1, owner);
        ch_idx[r] = idx;
        ch_l[r]   = (idx < 32) ? rawA : rawB;
        if (lane == owner) { if (idx < 32) s0 = -INFINITY; else s1 = -INFINITY; }
    }
    if (lane == 0) {
        float m = ch_l[0];
#pragma unroll
        for (int r = 1; r < TOPK; r++) m = fmaxf(m, ch_l[r]);
        float w[TOPK], sum = 0.f;
#pragma unroll
        for (int r = 0; r < TOPK; r++) { w[r] = expf(ch_l[r] - m); sum += w[r]; }
        float inv = 1.f / sum;
#pragma unroll
        for (int r = 0; r < TOPK; r++) {
            g_topk_idx[n * TOPK + r] = ch_idx[r];
            g_topk_w[n * TOPK + r]   = w[r] * inv;
        }
    }
}

// ===========================================================================
// 3) Dispatch (atomic slots; order-free, no overflow in practice)
// ===========================================================================
__global__ __launch_bounds__(256)
void k_dispatch_atomic()
{
    int p = blockIdx.x * 256 + threadIdx.x;
    int e = g_topk_idx[p];
    int slot = atomicAdd(&g_counts[e], 1);
    if (slot < CAP) {
        g_tok_table[e * CAP + slot] = p >> 2;
        g_pair_slot[p] = e * CAP + slot;
    } else {
        g_pair_slot[p] = -1;
    }
}

__global__ void k_tail_fill()
{
    int e = blockIdx.x;
    int cnt = g_counts[e]; if (cnt > CAP) cnt = CAP;
    for (int i = cnt + threadIdx.x; i < CAP; i += 256)
        g_tok_table[e * CAP + i] = 0;
    if (threadIdx.x == 0) g_counts[e] = cnt;
}

// ===========================================================================
// Consumer compute cores (single fp16 term both sides)
// ===========================================================================
// GU: 8 consumer warps on 128Mx64N; warp tile 32Mx32N
__device__ __forceinline__ void gu_cons(uint32_t ub,
    uint32_t offA0, uint32_t offA1, uint32_t offB,
    float ag[2][4][4], float au[2][4][4])
{
    const uint32_t uA = ub, uBg = ub + ABYTES, uBu = uBg + BBYTES;
#pragma unroll
    for (int ks = 0; ks < 4; ks++) {
        uint32_t kb = ks * 32;
        uint32_t ah[2][4], bg[8], bu[8];
        ldsm4(ah[0], uA + offA0 + kb); ldsm4(ah[1], uA + offA1 + kb);
        ldsm4(bg,     uBg + offB + kb); ldsm4(bg + 4, uBg + offB + 16 * SST_B + kb);
        ldsm4(bu,     uBu + offB + kb); ldsm4(bu + 4, uBu + offB + 16 * SST_B + kb);
#pragma unroll
        for (int mf = 0; mf < 2; mf++)
#pragma unroll
            for (int nf = 0; nf < 4; nf++) {
                mma_f16(ag[mf][nf], ah[mf], &bg[nf * 2]);
                mma_f16(au[mf][nf], ah[mf], &bu[nf * 2]);
            }
    }
}

// DN: 8 consumer warps on 128Mx128N; warp tile 32Mx64N
__device__ __forceinline__ void dn_cons(uint32_t ub,
    uint32_t offA0, uint32_t offA1, uint32_t offB,
    float ac[2][8][4])
{
    const uint32_t uA = ub, uB = ub + ABYTES;
#pragma unroll
    for (int ks = 0; ks < 4; ks++) {
        uint32_t kb = ks * 32;
        uint32_t ah[2][4], bh[16];
        ldsm4(ah[0], uA + offA0 + kb); ldsm4(ah[1], uA + offA1 + kb);
#pragma unroll
        for (int q = 0; q < 4; q++)
            ldsm4(bh + 4 * q, uB + offB + q * 16 * SST_B + kb);
#pragma unroll
        for (int mf = 0; mf < 2; mf++)
#pragma unroll
            for (int nf = 0; nf < 8; nf++)
                mma_f16(ac[mf][nf], ah[mf], &bh[nf * 2]);
    }
}

// ===========================================================================
// GU kernels (warp-specialized): warps 0-7 consumers, 8-15 producers
// ===========================================================================
__global__ __launch_bounds__(512)
void k_sh_gu(const float* __restrict__ sgw, const float* __restrict__ suw)
{
    extern __shared__ char sm[];
    const int tid = threadIdx.x, wid = tid >> 5, lane = tid & 31;
    const int t0 = blockIdx.x * 128, f0 = blockIdx.y * 64, s = blockIdx.z;
    uint32_t smb = smem_u32(sm);
    const int NIT = DM / 64;

    if (wid < 8) {
        const int wm = (wid >> 1) * 32, wn = (wid & 1) * 32;
        const uint32_t offA0 = (uint32_t)(wm + (lane & 15)) * SST_B + (lane >> 4) * 16;
        const uint32_t offA1 = offA0 + 16 * SST_B;
        const uint32_t offB  = (uint32_t)(wn + ((lane >> 4) << 3) + (lane & 7)) * SST_B
                             + ((lane >> 3) & 1) * 16;
        float ag[2][4][4] = {}, au[2][4][4] = {};
        for (int it = 0; it < NIT; it++) {
            int st = it % S_STAGES;
            BAR_SYNC(1 + st);
            gu_cons(smb + st * GU_STG, offA0, offA1, offB, ag, au);
            BAR_ARRIVE(4 + st);
        }
        const int rl = lane >> 2, cp = (lane & 3) * 2;
#pragma unroll
        for (int mf = 0; mf < 2; mf++)
#pragma unroll
            for (int nf = 0; nf < 4; nf++) {
                int row = t0 + wm + mf * 16 + rl;
                int col = f0 + wn + nf * 8 + cp;
                __half* b0 = g_hs + ((size_t)s * NT + row) * SFF + col;
                *(__half2*)b0 = __floats2half2_rn(silu_f(ag[mf][nf][0]) * au[mf][nf][0],
                                                  silu_f(ag[mf][nf][1]) * au[mf][nf][1]);
                *(__half2*)(b0 + (size_t)8 * SFF) =
                                __floats2half2_rn(silu_f(ag[mf][nf][2]) * au[mf][nf][2],
                                                  silu_f(ag[mf][nf][3]) * au[mf][nf][3]);
            }
    } else {
        const int ptid = tid - 256;
        const __half* Asrc = g_xh + (size_t)t0 * DM;
        const float*  Gsrc = sgw + ((size_t)s * SFF + f0) * DM;
        const float*  Usrc = suw + ((size_t)s * SFF + f0) * DM;
        uint4 va[4]; float4 vg[4], vu[4];
#pragma unroll
        for (int j = 0; j < 4; j++) {
            int ia = ptid + j * 256;
            va[j] = *(const uint4*)(Asrc + (size_t)(ia >> 3) * DM + ((ia & 7) << 3));
            vg[j] = *(const float4*)(Gsrc + (size_t)(ia >> 4) * DM + ((ia & 15) << 2));
            vu[j] = *(const float4*)(Usrc + (size_t)(ia >> 4) * DM + ((ia & 15) << 2));
        }
        for (int it = 0; it < NIT; it++) {
            int st = it % S_STAGES;
            if (it >= S_STAGES) BAR_SYNC(4 + st);
            char* base = sm + st * GU_STG;
            char* A = base; char* Bg = base + ABYTES; char* Bu = Bg + BBYTES;
#pragma unroll
            for (int j = 0; j < 4; j++) {
                int ia = ptid + j * 256;
                copy_storeA(va[j], A, ia >> 3, (ia & 7) << 3);
                cvt_storeBh(vg[j], Bg, ia >> 4, (ia & 15) << 2);
                cvt_storeBh(vu[j], Bu, ia >> 4, (ia & 15) << 2);
            }
            BAR_ARRIVE(1 + st);
            if (it + 1 < NIT) {
                int kt = (it + 1) * 64;
#pragma unroll
                for (int j = 0; j < 4; j++) {
                    int ia = ptid + j * 256;
                    va[j] = *(const uint4*)(Asrc + (size_t)(ia >> 3) * DM + kt + ((ia & 7) << 3));
                    vg[j] = *(const float4*)(Gsrc + (size_t)(ia >> 4) * DM + kt + ((ia & 15) << 2));
                    vu[j] = *(const float4*)(Usrc + (size_t)(ia >> 4) * DM + kt + ((ia & 15) << 2));
                }
            }
        }
    }
}

__global__ __launch_bounds__(512)
void k_ex_gu(const float* __restrict__ gw, const float* __restrict__ uw)
{
    const int e = blockIdx.x;
    const int t0 = blockIdx.y * 128, f0 = blockIdx.z * 64;
    if (t0 >= g_counts[e]) return;

    extern __shared__ char sm[];
    __shared__ int toks[128];
    const int tid = threadIdx.x, wid = tid >> 5, lane = tid & 31;
    uint32_t smb = smem_u32(sm);
    const int NIT = DM / 64;

    if (tid < 128) toks[tid] = g_tok_table[e * CAP + t0 + tid];
    __syncthreads();

    if (wid < 8) {
        const int wm = (wid >> 1) * 32, wn = (wid & 1) * 32;
        const uint32_t offA0 = (uint32_t)(wm + (lane & 15)) * SST_B + (lane >> 4) * 16;
        const uint32_t offA1 = offA0 + 16 * SST_B;
        const uint32_t offB  = (uint32_t)(wn + ((lane >> 4) << 3) + (lane & 7)) * SST_B
                             + ((lane >> 3) & 1) * 16;
        float ag[2][4][4] = {}, au[2][4][4] = {};
        for (int it = 0; it < NIT; it++) {
            int st = it % S_STAGES;
            BAR_SYNC(1 + st);
            gu_cons(smb + st * GU_STG, offA0, offA1, offB, ag, au);
            BAR_ARRIVE(4 + st);
        }
        const int rl = lane >> 2, cp = (lane & 3) * 2;
#pragma unroll
        for (int mf = 0; mf < 2; mf++)
#pragma unroll
            for (int nf = 0; nf < 4; nf++) {
                int row = t0 + wm + mf * 16 + rl;
                int col = f0 + wn + nf * 8 + cp;
                __half* b0 = g_h + ((size_t)e * CAP + row) * FF + col;
                *(__half2*)b0 = __floats2half2_rn(silu_f(ag[mf][nf][0]) * au[mf][nf][0],
                                                  silu_f(ag[mf][nf][1]) * au[mf][nf][1]);
                *(__half2*)(b0 + (size_t)8 * FF) =
                                __floats2half2_rn(silu_f(ag[mf][nf][2]) * au[mf][nf][2],
                                                  silu_f(ag[mf][nf][3]) * au[mf][nf][3]);
            }
    } else {
        const int ptid = tid - 256;
        const float* Gsrc = gw + ((size_t)e * FF + f0) * DM;
        const float* Usrc = uw + ((size_t)e * FF + f0) * DM;
        uint4 va[4]; float4 vg[4], vu[4];
#pragma unroll
        for (int j = 0; j < 4; j++) {
            int ia = ptid + j * 256;
            va[j] = *(const uint4*)(g_xh + (size_t)toks[ia >> 3] * DM + ((ia & 7) << 3));
            vg[j] = *(const float4*)(Gsrc + (size_t)(ia >> 4) * DM + ((ia & 15) << 2));
            vu[j] = *(const float4*)(Usrc + (size_t)(ia >> 4) * DM + ((ia & 15) << 2));
        }
        for (int it = 0; it < NIT; it++) {
            int st = it % S_STAGES;
            if (it >= S_STAGES) BAR_SYNC(4 + st);
            char* base = sm + st * GU_STG;
            char* A = base; char* Bg = base + ABYTES; char* Bu = Bg + BBYTES;
#pragma unroll
            for (int j = 0; j < 4; j++) {
                int ia = ptid + j * 256;
                copy_storeA(va[j], A, ia >> 3, (ia & 7) << 3);
                cvt_storeBh(vg[j], Bg, ia >> 4, (ia & 15) << 2);
                cvt_storeBh(vu[j], Bu, ia >> 4, (ia & 15) << 2);
            }
            BAR_ARRIVE(1 + st);
            if (it + 1 < NIT) {
                int kt = (it + 1) * 64;
#pragma unroll
                for (int j = 0; j < 4; j++) {
                    int ia = ptid + j * 256;
                    va[j] = *(const uint4*)(g_xh + (size_t)toks[ia >> 3] * DM + kt + ((ia & 7) << 3));
                    vg[j] = *(const float4*)(Gsrc + (size_t)(ia >> 4) * DM + kt + ((ia & 15) << 2));
                    vu[j] = *(const float4*)(Usrc + (size_t)(ia >> 4) * DM + kt + ((ia & 15) << 2));
                }
            }
        }
    }
}

// ===========================================================================
// DN kernels (warp-specialized), CTA 128Mx128N
// ===========================================================================
__global__ __launch_bounds__(512)
void k_sh_dn(const float* __restrict__ sdw, float* __restrict__ out)
{
    extern __shared__ char sm[];
    const int tid = threadIdx.x, wid = tid >> 5, lane = tid & 31;
    const int t0 = blockIdx.x * 128, d0 = blockIdx.y * 128;
    uint32_t smb = smem_u32(sm);
    const int NIT = 64;

    if (wid < 8) {
        const int wm = (wid >> 1) * 32, wn = (wid & 1) * 64;
        const uint32_t offA0 = (uint32_t)(wm + (lane & 15)) * SST_B + (lane >> 4) * 16;
        const uint32_t offA1 = offA0 + 16 * SST_B;
        const uint32_t offB  = (uint32_t)(wn + ((lane >> 4) << 3) + (lane & 7)) * SST_B
                             + ((lane >> 3) & 1) * 16;
        float ac[2][8][4] = {};
        for (int it = 0; it < NIT; it++) {
            int st = it % S_STAGES;
            BAR_SYNC(1 + st);
            dn_cons(smb + st * DN_STG, offA0, offA1, offB, ac);
            BAR_ARRIVE(4 + st);
        }
        const int rl = lane >> 2, cp = (lane & 3) * 2;
#pragma unroll
        for (int mf = 0; mf < 2; mf++)
#pragma unroll
            for (int nf = 0; nf < 8; nf++) {
                int row = t0 + wm + mf * 16 + rl;
                int col = d0 + wn + nf * 8 + cp;
                float* b0 = out + (size_t)row * DM + col;
                *(float2*)b0 = make_float2(ac[mf][nf][0], ac[mf][nf][1]);
                *(float2*)(b0 + (size_t)8 * DM) = make_float2(ac[mf][nf][2], ac[mf][nf][3]);
            }
    } else {
        const int ptid = tid - 256;
        uint4 va[4]; float4 vb[8];
#pragma unroll
        for (int j = 0; j < 4; j++) {
            int ia = ptid + j * 256;
            va[j] = *(const uint4*)(g_hs + ((size_t)t0 + (ia >> 3)) * SFF + ((ia & 7) << 3));
        }
#pragma unroll
        for (int j = 0; j < 8; j++) {
            int ib = ptid + j * 256;
            vb[j] = *(const float4*)(sdw + ((size_t)d0 + (ib >> 4)) * SFF + ((ib & 15) << 2));
        }
        for (int it = 0; it < NIT; it++) {
            int st = it % S_STAGES;
            if (it >= S_STAGES) BAR_SYNC(4 + st);
            char* base = sm + st * DN_STG;
            char* A = base; char* B = base + ABYTES;
#pragma unroll
            for (int j = 0; j < 4; j++) {
                int ia = ptid + j * 256;
                copy_storeA(va[j], A, ia >> 3, (ia & 7) << 3);
            }
#pragma unroll
            for (int j = 0; j < 8; j++) {
                int ib = ptid + j * 256;
                cvt_storeBh(vb[j], B, ib >> 4, (ib & 15) << 2);
            }
            BAR_ARRIVE(1 + st);
            if (it + 1 < NIT) {
                int s2 = (it + 1) >> 5;
                int kt = ((it + 1) & 31) * 64;
#pragma unroll
                for (int j = 0; j < 4; j++) {
                    int ia = ptid + j * 256;
                    va[j] = *(const uint4*)(g_hs + ((size_t)s2 * NT + t0 + (ia >> 3)) * SFF + kt + ((ia & 7) << 3));
                }
#pragma unroll
                for (int j = 0; j < 8; j++) {
                    int ib = ptid + j * 256;
                    vb[j] = *(const float4*)(sdw + ((size_t)s2 * DM + d0 + (ib >> 4)) * SFF + kt + ((ib & 15) << 2));
                }
            }
        }
    }
}

__global__ __launch_bounds__(512)
void k_ex_dn(const float* __restrict__ dw)
{
    const int e = blockIdx.x;
    const int t0 = blockIdx.y * 128, d0 = blockIdx.z * 128;
    if (t0 >= g_counts[e]) return;

    extern __shared__ char sm[];
    const int tid = threadIdx.x, wid = tid >> 5, lane = tid & 31;
    uint32_t smb = smem_u32(sm);
    const int NIT = FF / 64;

    if (wid < 8) {
        const int wm = (wid >> 1) * 32, wn = (wid & 1) * 64;
        const uint32_t offA0 = (uint32_t)(wm + (lane & 15)) * SST_B + (lane >> 4) * 16;
        const uint32_t offA1 = offA0 + 16 * SST_B;
        const uint32_t offB  = (uint32_t)(wn + ((lane >> 4) << 3) + (lane & 7)) * SST_B
                             + ((lane >> 3) & 1) * 16;
        float ac[2][8][4] = {};
        for (int it = 0; it < NIT; it++) {
            int st = it % S_STAGES;
            BAR_SYNC(1 + st);
            dn_cons(smb + st * DN_STG, offA0, offA1, offB, ac);
            BAR_ARRIVE(4 + st);
        }
        const int rl = lane >> 2, cp = (lane & 3) * 2;
#pragma unroll
        for (int mf = 0; mf < 2; mf++)
#pragma unroll
            for (int nf = 0; nf < 8; nf++) {
                int row = t0 + wm + mf * 16 + rl;
                int col = d0 + wn + nf * 8 + cp;
                float* b0 = g_y + ((size_t)e * CAP + row) * DM + col;
                *(float2*)b0 = make_float2(ac[mf][nf][0], ac[mf][nf][1]);
                *(float2*)(b0 + (size_t)8 * DM) = make_float2(ac[mf][nf][2], ac[mf][nf][3]);
            }
    } else {
        const int ptid = tid - 256;
        const __half* Asrc = g_h + ((size_t)e * CAP + t0) * FF;
        const float*  Bsrc = dw  + ((size_t)e * DM + d0) * FF;
        uint4 va[4]; float4 vb[8];
#pragma unroll
        for (int j = 0; j < 4; j++) {
            int ia = ptid + j * 256;
            va[j] = *(const uint4*)(Asrc + (size_t)(ia >> 3) * FF + ((ia & 7) << 3));
        }
#pragma unroll
        for (int j = 0; j < 8; j++) {
            int ib = ptid + j * 256;
            vb[j] = *(const float4*)(Bsrc + (size_t)(ib >> 4) * FF + ((ib & 15) << 2));
        }
        for (int it = 0; it < NIT; it++) {
            int st = it % S_STAGES;
            if (it >= S_STAGES) BAR_SYNC(4 + st);
            char* base = sm + st * DN_STG;
            char* A = base; char* B = base + ABYTES;
#pragma unroll
            for (int j = 0; j < 4; j++) {
                int ia = ptid + j * 256;
                copy_storeA(va[j], A, ia >> 3, (ia & 7) << 3);
            }
#pragma unroll
            for (int j = 0; j < 8; j++) {
                int ib = ptid + j * 256;
                cvt_storeBh(vb[j], B, ib >> 4, (ib & 15) << 2);
            }
            BAR_ARRIVE(1 + st);
            if (it + 1 < NIT) {
                int kt = (it + 1) * 64;
#pragma unroll
                for (int j = 0; j < 4; j++) {
                    int ia = ptid + j * 256;
                    va[j] = *(const uint4*)(Asrc + (size_t)(ia >> 3) * FF + kt + ((ia & 7) << 3));
                }
#pragma unroll
                for (int j = 0; j < 8; j++) {
                    int ib = ptid + j * 256;
                    vb[j] = *(const float4*)(Bsrc + (size_t)(ib >> 4) * FF + kt + ((ib & 15) << 2));
                }
            }
        }
    }
}

// ===========================================================================
// Combine
// ===========================================================================
__global__ __launch_bounds__(256)
void k_combine(float* __restrict__ out)
{
    const int n = blockIdx.x, tid = threadIdx.x;
    int sl[TOPK]; float w[TOPK];
#pragma unroll
    for (int r = 0; r < TOPK; r++) {
        sl[r] = g_pair_slot[n * TOPK + r];
        w[r]  = g_topk_w[n * TOPK + r];
    }
    float* orow = out + (size_t)n * DM;
#pragma unroll
    for (int d = tid * 4; d < DM; d += 1024) {
        float4 acc = *(float4*)(orow + d);
#pragma unroll
        for (int r = 0; r < TOPK; r++) {
            if (sl[r] >= 0) {
                float4 yv = *(const float4*)(g_y + (size_t)sl[r] * DM + d);
                acc.x += w[r] * yv.x; acc.y += w[r] * yv.y;
                acc.z += w[r] * yv.z; acc.w += w[r] * yv.w;
            }
        }
        *(float4*)(orow + d) = acc;
    }
}

// ===========================================================================
// Launch
// ===========================================================================
extern "C" void kernel_launch(void* const* d_in, const int* in_sizes, int n_in,
                              void* d_out, int out_size)
{
    const float* x      = (const float*)d_in[0];
    const float* rw     = (const float*)d_in[1];
    const float* rbias  = (const float*)d_in[2];
    const float* gate_w = (const float*)d_in[3];
    const float* up_w   = (const float*)d_in[4];
    const float* down_w = (const float*)d_in[5];
    const float* sg_w   = (const float*)d_in[6];
    const float* su_w   = (const float*)d_in[7];
    const float* sd_w   = (const float*)d_in[8];
    float* out = (float*)d_out;

    cudaFuncSetAttribute(k_sh_gu, cudaFuncAttributeMaxDynamicSharedMemorySize, GU_SMEM);
    cudaFuncSetAttribute(k_ex_gu, cudaFuncAttributeMaxDynamicSharedMemorySize, GU_SMEM);
    cudaFuncSetAttribute(k_sh_dn, cudaFuncAttributeMaxDynamicSharedMemorySize, DN_SMEM);
    cudaFuncSetAttribute(k_ex_dn, cudaFuncAttributeMaxDynamicSharedMemorySize, DN_SMEM);

    k_cvt_x<<<NT * DM / 1024, 256>>>(x);
    k_router_logits<<<NT / RBM, 256>>>(x, rw);
    k_topk<<<NT, 32>>>(rbias);
    k_dispatch_atomic<<<NP / 256, 256>>>();
    k_tail_fill<<<NE, 256>>>();

    k_ex_gu<<<dim3(NE, CAP / 128, FF / 64), 512, GU_SMEM>>>(gate_w, up_w);
    k_sh_gu<<<dim3(NT / 128, SFF / 64, NS), 512, GU_SMEM>>>(sg_w, su_w);

    k_sh_dn<<<dim3(NT / 128, DM / 128), 512, DN_SMEM>>>(sd_w, out);
    k_ex_dn<<<dim3(NE, CAP / 128, DM / 128), 512, DN_SMEM>>>(down_w);

    k_combine<<<NT, 256>>>(out);
}